// round 4
// baseline (speedup 1.0000x reference)
#include <cuda_runtime.h>
#include <cuda_bf16.h>
#include <math.h>
#include <stdint.h>

#define Nn 50000
#define Ee 400000
#define Pp 3

// ---------------- scratch (device globals) --------------------------------------
__device__ __align__(16) float g_x[(size_t)Nn * 128];
__device__ __align__(16) float g_feat[(size_t)Pp * Nn * 128];
__device__ __align__(16) float g_z[(size_t)Pp * Nn * 128];
__device__ __align__(16) float g_el[(size_t)Pp * Nn * 4];
__device__ __align__(16) float g_er[(size_t)Pp * Nn * 4];
__device__ int g_deg[(size_t)Pp * Nn];
__device__ int g_off[(size_t)Pp * (Nn + 1)];
__device__ int g_cur[(size_t)Pp * Nn];
__device__ int g_csrc[(size_t)Pp * Ee];
__device__ __align__(16) __nv_bfloat16 g_bt_hi[4 * 128 * 128];  // [slot][n][k], slots 0..2 gat_W^T, 3 sa_w1^T
__device__ __align__(16) __nv_bfloat16 g_bt_lo[4 * 128 * 128];
__device__ float g_wsem[Pp];
__device__ float g_bsem[Pp];

// ---------------- smem layout for GEMM kernels (bf16, padded rows of 136) --------
#define SROW 136
#define S_AUX0 0          // 128 floats
#define S_AUX1 512        // 128 floats
#define S_RED  1024       // 8 floats
#define S_AH   2048
#define S_AL   (S_AH + 128 * SROW * 2)     // 36864
#define S_BH   (S_AL + 128 * SROW * 2)     // 71680
#define S_BL   (S_BH + 128 * SROW * 2)     // 106496
#define SMEM_TOT (S_BL + 128 * SROW * 2)   // 141312

__device__ __forceinline__ void mma16816(float& d0, float& d1, float& d2, float& d3,
                                         uint32_t a0, uint32_t a1, uint32_t a2, uint32_t a3,
                                         uint32_t b0, uint32_t b1) {
    asm volatile(
        "mma.sync.aligned.m16n8k16.row.col.f32.bf16.bf16.f32 "
        "{%0,%1,%2,%3}, {%4,%5,%6,%7}, {%8,%9}, {%0,%1,%2,%3};"
        : "+f"(d0), "+f"(d1), "+f"(d2), "+f"(d3)
        : "r"(a0), "r"(a1), "r"(a2), "r"(a3), "r"(b0), "r"(b1));
}

__device__ __forceinline__ uint32_t bf2u(__nv_bfloat162 v) {
    return *reinterpret_cast<uint32_t*>(&v);
}

// fill A (hi/lo split of fp32 rows) and B (prebuilt bf16 hi/lo) tiles, then run
// 3 passes x 8 k-steps of m16n8k16 accumulating into d[2][8][4].
__device__ __forceinline__ void gemm_core(const float* __restrict__ Xsrc, int n0,
                                          const __nv_bfloat16* __restrict__ bth,
                                          const __nv_bfloat16* __restrict__ btl,
                                          char* smem, float d[2][8][4]) {
    int tid = threadIdx.x, lane = tid & 31, wid = tid >> 5;
    int warpM = wid & 3, warpN = wid >> 2;
    // A: 128 rows x 128 cols fp32 -> hi/lo bf16
    for (int idx = tid; idx < 128 * 32; idx += 256) {
        int row = idx >> 5;
        int c4 = idx & 31;
        int n = n0 + row;
        float4 v = make_float4(0.f, 0.f, 0.f, 0.f);
        if (n < Nn) v = *(const float4*)&Xsrc[(size_t)n * 128 + c4 * 4];
        __nv_bfloat162 h0 = __floats2bfloat162_rn(v.x, v.y);
        __nv_bfloat162 h1 = __floats2bfloat162_rn(v.z, v.w);
        float2 f0 = __bfloat1622float2(h0), f1 = __bfloat1622float2(h1);
        __nv_bfloat162 l0 = __floats2bfloat162_rn(v.x - f0.x, v.y - f0.y);
        __nv_bfloat162 l1 = __floats2bfloat162_rn(v.z - f1.x, v.w - f1.y);
        size_t off = ((size_t)row * SROW + c4 * 4) * 2;
        *(uint2*)(smem + S_AH + off) = make_uint2(bf2u(h0), bf2u(h1));
        *(uint2*)(smem + S_AL + off) = make_uint2(bf2u(l0), bf2u(l1));
    }
    // B: [n][k] bf16 hi/lo -> padded smem
    for (int idx = tid; idx < 128 * 16; idx += 256) {
        int row = idx >> 4;
        int q = idx & 15;
        size_t off = ((size_t)row * SROW + q * 8) * 2;
        *(uint4*)(smem + S_BH + off) = *(const uint4*)(bth + (size_t)row * 128 + q * 8);
        *(uint4*)(smem + S_BL + off) = *(const uint4*)(btl + (size_t)row * 128 + q * 8);
    }
    __syncthreads();

    int arow = warpM * 32 + (lane >> 2);
    int acol = (lane & 3) * 2;
    int brow = warpN * 64 + (lane >> 2);
    int bcol = (lane & 3) * 2;
#pragma unroll
    for (int pass = 0; pass < 3; pass++) {
        const char* pA = smem + ((pass == 2) ? S_AL : S_AH);
        const char* pB = smem + ((pass == 1) ? S_BL : S_BH);
#pragma unroll
        for (int ks = 0; ks < 8; ks++) {
            int k0 = ks * 16;
            uint32_t af[2][4];
#pragma unroll
            for (int mt = 0; mt < 2; mt++) {
                const char* base = pA + ((size_t)(arow + mt * 16) * SROW + k0 + acol) * 2;
                af[mt][0] = *(const uint32_t*)(base);
                af[mt][1] = *(const uint32_t*)(base + 8 * SROW * 2);
                af[mt][2] = *(const uint32_t*)(base + 16);
                af[mt][3] = *(const uint32_t*)(base + 8 * SROW * 2 + 16);
            }
#pragma unroll
            for (int nt = 0; nt < 8; nt++) {
                const char* base = pB + ((size_t)(brow + nt * 8) * SROW + k0 + bcol) * 2;
                uint32_t b0 = *(const uint32_t*)(base);
                uint32_t b1 = *(const uint32_t*)(base + 16);
#pragma unroll
                for (int mt = 0; mt < 2; mt++)
                    mma16816(d[mt][nt][0], d[mt][nt][1], d[mt][nt][2], d[mt][nt][3],
                             af[mt][0], af[mt][1], af[mt][2], af[mt][3], b0, b1);
            }
        }
    }
}

// ---------------- projection GEMM + fused el/er -----------------------------------
__global__ void __launch_bounds__(256) k_gemm_feat(
    const float* __restrict__ x, const __nv_bfloat16* __restrict__ bth,
    const __nv_bfloat16* __restrict__ btl, const float* __restrict__ al,
    const float* __restrict__ ar, float* __restrict__ feat, float* __restrict__ el,
    float* __restrict__ er) {
    extern __shared__ char smem[];
    int tid = threadIdx.x, lane = tid & 31, wid = tid >> 5;
    int warpM = wid & 3, warpN = wid >> 2;
    int p = blockIdx.y;
    int n0 = blockIdx.x * 128;
    float* sal = (float*)(smem + S_AUX0);
    float* sar = (float*)(smem + S_AUX1);
    if (tid < 128) { sal[tid] = al[p * 128 + tid]; sar[tid] = ar[p * 128 + tid]; }

    float d[2][8][4];
#pragma unroll
    for (int mt = 0; mt < 2; mt++)
#pragma unroll
        for (int nt = 0; nt < 8; nt++)
#pragma unroll
            for (int q = 0; q < 4; q++) d[mt][nt][q] = 0.f;

    gemm_core(x, n0, bth + (size_t)p * 16384, btl + (size_t)p * 16384, smem, d);

    // epilogue: store feat + per-head el/er partial dots
    int rq = lane >> 2;            // 0..7
    int cq = (lane & 3) * 2;       // 0,2,4,6
#pragma unroll
    for (int mt = 0; mt < 2; mt++) {
        int r0 = n0 + warpM * 32 + mt * 16 + rq;   // row of d0,d1
        int r1 = r0 + 8;                           // row of d2,d3
        float pel0 = 0.f, pel1 = 0.f, per0 = 0.f, per1 = 0.f;  // [row0/1][head within pair]
        float qel0 = 0.f, qel1 = 0.f, qer0 = 0.f, qer1 = 0.f;
#pragma unroll
        for (int nt = 0; nt < 8; nt++) {
            int c = warpN * 64 + nt * 8 + cq;      // global col of d0/d2; d1/d3 = c+1
            float w0 = sal[c], w1 = sal[c + 1];
            float v0 = sar[c], v1 = sar[c + 1];
            if (r0 < Nn) {
                float2* o = (float2*)&feat[((size_t)p * Nn + r0) * 128 + c];
                *o = make_float2(d[mt][nt][0], d[mt][nt][1]);
            }
            if (r1 < Nn) {
                float2* o = (float2*)&feat[((size_t)p * Nn + r1) * 128 + c];
                *o = make_float2(d[mt][nt][2], d[mt][nt][3]);
            }
            if (nt < 4) {
                pel0 = fmaf(d[mt][nt][0], w0, pel0); pel0 = fmaf(d[mt][nt][1], w1, pel0);
                per0 = fmaf(d[mt][nt][0], v0, per0); per0 = fmaf(d[mt][nt][1], v1, per0);
                qel0 = fmaf(d[mt][nt][2], w0, qel0); qel0 = fmaf(d[mt][nt][3], w1, qel0);
                qer0 = fmaf(d[mt][nt][2], v0, qer0); qer0 = fmaf(d[mt][nt][3], v1, qer0);
            } else {
                pel1 = fmaf(d[mt][nt][0], w0, pel1); pel1 = fmaf(d[mt][nt][1], w1, pel1);
                per1 = fmaf(d[mt][nt][0], v0, per1); per1 = fmaf(d[mt][nt][1], v1, per1);
                qel1 = fmaf(d[mt][nt][2], w0, qel1); qel1 = fmaf(d[mt][nt][3], w1, qel1);
                qer1 = fmaf(d[mt][nt][2], v0, qer1); qer1 = fmaf(d[mt][nt][3], v1, qer1);
            }
        }
        // quad reduce (lanes 4q..4q+3 share row)
#pragma unroll
        for (int o = 1; o <= 2; o <<= 1) {
            pel0 += __shfl_xor_sync(0xffffffffu, pel0, o);
            pel1 += __shfl_xor_sync(0xffffffffu, pel1, o);
            per0 += __shfl_xor_sync(0xffffffffu, per0, o);
            per1 += __shfl_xor_sync(0xffffffffu, per1, o);
            qel0 += __shfl_xor_sync(0xffffffffu, qel0, o);
            qel1 += __shfl_xor_sync(0xffffffffu, qel1, o);
            qer0 += __shfl_xor_sync(0xffffffffu, qer0, o);
            qer1 += __shfl_xor_sync(0xffffffffu, qer1, o);
        }
        if ((lane & 3) == 0) {
            if (r0 < Nn) {
                *(float2*)&el[((size_t)p * Nn + r0) * 4 + warpN * 2] = make_float2(pel0, pel1);
                *(float2*)&er[((size_t)p * Nn + r0) * 4 + warpN * 2] = make_float2(per0, per1);
            }
            if (r1 < Nn) {
                *(float2*)&el[((size_t)p * Nn + r1) * 4 + warpN * 2] = make_float2(qel0, qel1);
                *(float2*)&er[((size_t)p * Nn + r1) * 4 + warpN * 2] = make_float2(qer0, qer1);
            }
        }
    }
}

// ---------------- semantic GEMM + tanh/w2 reduce ------------------------------------
__global__ void __launch_bounds__(256) k_semgemm(
    const float* __restrict__ z, const __nv_bfloat16* __restrict__ bth,
    const __nv_bfloat16* __restrict__ btl, const float* __restrict__ b1,
    const float* __restrict__ w2, float* __restrict__ wsem) {
    extern __shared__ char smem[];
    int tid = threadIdx.x, lane = tid & 31, wid = tid >> 5;
    int warpM = wid & 3, warpN = wid >> 2;
    int p = blockIdx.y;
    int n0 = blockIdx.x * 128;
    float* sb1 = (float*)(smem + S_AUX0);
    float* sw2 = (float*)(smem + S_AUX1);
    float* sred = (float*)(smem + S_RED);
    if (tid < 128) { sb1[tid] = b1[tid]; sw2[tid] = w2[tid]; }

    float d[2][8][4];
#pragma unroll
    for (int mt = 0; mt < 2; mt++)
#pragma unroll
        for (int nt = 0; nt < 8; nt++)
#pragma unroll
            for (int q = 0; q < 4; q++) d[mt][nt][q] = 0.f;

    gemm_core(z + (size_t)p * Nn * 128, n0, bth, btl, smem, d);

    int rq = lane >> 2, cq = (lane & 3) * 2;
    float accv = 0.f;
#pragma unroll
    for (int mt = 0; mt < 2; mt++) {
        int r0 = n0 + warpM * 32 + mt * 16 + rq;
        int r1 = r0 + 8;
        bool v0 = r0 < Nn, v1 = r1 < Nn;
#pragma unroll
        for (int nt = 0; nt < 8; nt++) {
            int c = warpN * 64 + nt * 8 + cq;
            if (v0) {
                accv = fmaf(tanhf(d[mt][nt][0] + sb1[c]), sw2[c], accv);
                accv = fmaf(tanhf(d[mt][nt][1] + sb1[c + 1]), sw2[c + 1], accv);
            }
            if (v1) {
                accv = fmaf(tanhf(d[mt][nt][2] + sb1[c]), sw2[c], accv);
                accv = fmaf(tanhf(d[mt][nt][3] + sb1[c + 1]), sw2[c + 1], accv);
            }
        }
    }
#pragma unroll
    for (int o = 16; o; o >>= 1) accv += __shfl_xor_sync(0xffffffffu, accv, o);
    if (lane == 0) sred[wid] = accv;
    __syncthreads();
    if (tid == 0) {
        float s = 0.f;
#pragma unroll
        for (int i = 0; i < 8; i++) s += sred[i];
        atomicAdd(&wsem[p], s);
    }
}

// ---------------- feature attention: warp per node ----------------------------------
__global__ void k_featatt(const float* __restrict__ h, const float* __restrict__ cf,
                          const float* __restrict__ w1, const float* __restrict__ b1,
                          const float* __restrict__ w2, float* __restrict__ x) {
    __shared__ float sw1[42 * 16];
    __shared__ float sb1[16], sw2[16];
    __shared__ float sf[8][840];
    __shared__ float ss[8][20];
    int tid = threadIdx.x, wid = tid >> 5, lane = tid & 31;
    for (int i = tid; i < 672; i += 256) sw1[i] = w1[i];
    if (tid < 16) { sb1[tid] = b1[tid]; sw2[tid] = w2[tid]; }
    __syncthreads();
    int n = blockIdx.x * 8 + wid;
    if (n >= Nn) return;

    const float* fr = cf + (size_t)n * 840;
    float* myf = sf[wid];
    for (int i = lane; i < 840; i += 32) myf[i] = fr[i];
    __syncwarp();

    int k = lane & 15;
    for (int j0 = 0; j0 < 20; j0 += 2) {
        int j = j0 + (lane >> 4);
        const float* fj = myf + j * 42;
        float acc = sb1[k];
#pragma unroll
        for (int i = 0; i < 42; i++) acc = fmaf(fj[i], sw1[i * 16 + k], acc);
        float v = tanhf(acc) * sw2[k];
#pragma unroll
        for (int off = 8; off; off >>= 1) v += __shfl_down_sync(0xffffffffu, v, off);
        if (k == 0) ss[wid][j] = v;
    }
    __syncwarp();

    float sc = (lane < 20) ? ss[wid][lane] : -INFINITY;
    float mx = sc;
#pragma unroll
    for (int off = 16; off; off >>= 1) mx = fmaxf(mx, __shfl_xor_sync(0xffffffffu, mx, off));
    float ex = (lane < 20) ? expf(sc - mx) : 0.f;
    float sm = ex;
#pragma unroll
    for (int off = 16; off; off >>= 1) sm += __shfl_xor_sync(0xffffffffu, sm, off);
    float beta = ex / sm;

    float a0 = 0.f, a1 = 0.f;
    for (int j = 0; j < 20; j++) {
        float bj = __shfl_sync(0xffffffffu, beta, j);
        a0 = fmaf(bj, myf[j * 42 + lane], a0);
        if (lane < 10) a1 = fmaf(bj, myf[j * 42 + 32 + lane], a1);
    }
    float* xr = x + (size_t)n * 128;
    const float* hr = h + (size_t)n * 86;
    for (int i = lane; i < 86; i += 32) xr[i] = hr[i];
    xr[86 + lane] = a0;
    if (lane < 10) xr[118 + lane] = a1;
}

// ---------------- weight prep: transpose + bf16 hi/lo split --------------------------
__global__ void k_wprep(const float* __restrict__ gatW, const float* __restrict__ saw1,
                        __nv_bfloat16* __restrict__ bh, __nv_bfloat16* __restrict__ bl) {
    int idx = blockIdx.x * 256 + threadIdx.x;
    if (idx >= 4 * 16384) return;
    int slot = idx >> 14, rem = idx & 16383;
    int nIdx = rem >> 7, kIdx = rem & 127;
    float v = (slot < 3) ? gatW[slot * 16384 + kIdx * 128 + nIdx] : saw1[kIdx * 128 + nIdx];
    __nv_bfloat16 hh = __float2bfloat16(v);
    bh[idx] = hh;
    bl[idx] = __float2bfloat16(v - __bfloat162float(hh));
}

// ---------------- CSR build -----------------------------------------------------------
__global__ void k_count(const int* __restrict__ dst, int* __restrict__ deg) {
    int p = blockIdx.y;
    int e = blockIdx.x * 256 + threadIdx.x;
    if (e >= Ee) return;
    atomicAdd(&deg[(size_t)p * Nn + dst[(size_t)p * Ee + e]], 1);
}

__global__ void k_scan(const int* __restrict__ deg, int* __restrict__ off,
                       int* __restrict__ cur) {
    int p = blockIdx.x;
    int tid = threadIdx.x, lane = tid & 31, wid = tid >> 5;
    __shared__ int wsum[32];
    __shared__ int carry;
    if (tid == 0) carry = 0;
    __syncthreads();
    for (int base = 0; base < Nn; base += 1024) {
        int i = base + tid;
        int v = (i < Nn) ? deg[(size_t)p * Nn + i] : 0;
        int xv = v;
#pragma unroll
        for (int o = 1; o < 32; o <<= 1) {
            int t = __shfl_up_sync(0xffffffffu, xv, o);
            if (lane >= o) xv += t;
        }
        if (lane == 31) wsum[wid] = xv;
        __syncthreads();
        if (wid == 0) {
            int y = wsum[lane];
#pragma unroll
            for (int o = 1; o < 32; o <<= 1) {
                int t = __shfl_up_sync(0xffffffffu, y, o);
                if (lane >= o) y += t;
            }
            wsum[lane] = y;
        }
        __syncthreads();
        int wpre = (wid == 0) ? 0 : wsum[wid - 1];
        int excl = carry + wpre + xv - v;
        if (i < Nn) {
            off[(size_t)p * (Nn + 1) + i] = excl;
            cur[(size_t)p * Nn + i] = excl;
        }
        __syncthreads();
        if (tid == 1023) carry = excl + v;
        __syncthreads();
    }
    if (tid == 0) off[(size_t)p * (Nn + 1) + Nn] = carry;
}

__global__ void k_scatter(const int* __restrict__ src, const int* __restrict__ dst,
                          int* __restrict__ cur, int* __restrict__ csrc) {
    int p = blockIdx.y;
    int e = blockIdx.x * 256 + threadIdx.x;
    if (e >= Ee) return;
    int d = dst[(size_t)p * Ee + e];
    int pos = atomicAdd(&cur[(size_t)p * Nn + d], 1);
    csrc[(size_t)p * Ee + pos] = src[(size_t)p * Ee + e];
}

// ---------------- gather aggregation: warp per (p, dst) -------------------------------
__global__ void k_gather(const int* __restrict__ csrc, const int* __restrict__ off,
                         const float* __restrict__ el, const float* __restrict__ er,
                         const float* __restrict__ feat, float* __restrict__ z) {
    int p = blockIdx.y;
    int tid = threadIdx.x, wid = tid >> 5, lane = tid & 31;
    int n = blockIdx.x * 8 + wid;
    if (n >= Nn) return;
    long r = (long)p * Nn + n;
    int start = off[(size_t)p * (Nn + 1) + n];
    int end = off[(size_t)p * (Nn + 1) + n + 1];
    float* zp = &z[r * 128 + lane * 4];
    if (start == end) {
        *(float4*)zp = make_float4(0.f, 0.f, 0.f, 0.f);
        return;
    }
    const int* sp = csrc + (size_t)p * Ee;
    const float4* elp = (const float4*)el + (size_t)p * Nn;
    float4 er4 = ((const float4*)er)[r];

    float4 mx = make_float4(-INFINITY, -INFINITY, -INFINITY, -INFINITY);
    for (int i = start + lane; i < end; i += 32) {
        float4 a = elp[sp[i]];
        float vx = a.x + er4.x; vx = vx > 0.f ? vx : 0.2f * vx;
        float vy = a.y + er4.y; vy = vy > 0.f ? vy : 0.2f * vy;
        float vz = a.z + er4.z; vz = vz > 0.f ? vz : 0.2f * vz;
        float vw = a.w + er4.w; vw = vw > 0.f ? vw : 0.2f * vw;
        mx.x = fmaxf(mx.x, vx); mx.y = fmaxf(mx.y, vy);
        mx.z = fmaxf(mx.z, vz); mx.w = fmaxf(mx.w, vw);
    }
#pragma unroll
    for (int o = 16; o; o >>= 1) {
        mx.x = fmaxf(mx.x, __shfl_xor_sync(0xffffffffu, mx.x, o));
        mx.y = fmaxf(mx.y, __shfl_xor_sync(0xffffffffu, mx.y, o));
        mx.z = fmaxf(mx.z, __shfl_xor_sync(0xffffffffu, mx.z, o));
        mx.w = fmaxf(mx.w, __shfl_xor_sync(0xffffffffu, mx.w, o));
    }

    int head = lane >> 3;
    float4 acc = make_float4(0.f, 0.f, 0.f, 0.f);
    float4 zs = make_float4(0.f, 0.f, 0.f, 0.f);
    int i = start;
    for (; i + 1 < end; i += 2) {
        int s0 = sp[i], s1 = sp[i + 1];
        float4 a0 = elp[s0], a1 = elp[s1];
        float4 f0 = *(const float4*)&feat[((size_t)p * Nn + s0) * 128 + lane * 4];
        float4 f1 = *(const float4*)&feat[((size_t)p * Nn + s1) * 128 + lane * 4];
        float4 w0, w1;
        float t;
        t = a0.x + er4.x; t = t > 0.f ? t : 0.2f * t; w0.x = __expf(t - mx.x);
        t = a0.y + er4.y; t = t > 0.f ? t : 0.2f * t; w0.y = __expf(t - mx.y);
        t = a0.z + er4.z; t = t > 0.f ? t : 0.2f * t; w0.z = __expf(t - mx.z);
        t = a0.w + er4.w; t = t > 0.f ? t : 0.2f * t; w0.w = __expf(t - mx.w);
        t = a1.x + er4.x; t = t > 0.f ? t : 0.2f * t; w1.x = __expf(t - mx.x);
        t = a1.y + er4.y; t = t > 0.f ? t : 0.2f * t; w1.y = __expf(t - mx.y);
        t = a1.z + er4.z; t = t > 0.f ? t : 0.2f * t; w1.z = __expf(t - mx.z);
        t = a1.w + er4.w; t = t > 0.f ? t : 0.2f * t; w1.w = __expf(t - mx.w);
        zs.x += w0.x + w1.x; zs.y += w0.y + w1.y;
        zs.z += w0.z + w1.z; zs.w += w0.w + w1.w;
        float c0 = head == 0 ? w0.x : head == 1 ? w0.y : head == 2 ? w0.z : w0.w;
        float c1 = head == 0 ? w1.x : head == 1 ? w1.y : head == 2 ? w1.z : w1.w;
        acc.x = fmaf(c0, f0.x, acc.x); acc.x = fmaf(c1, f1.x, acc.x);
        acc.y = fmaf(c0, f0.y, acc.y); acc.y = fmaf(c1, f1.y, acc.y);
        acc.z = fmaf(c0, f0.z, acc.z); acc.z = fmaf(c1, f1.z, acc.z);
        acc.w = fmaf(c0, f0.w, acc.w); acc.w = fmaf(c1, f1.w, acc.w);
    }
    if (i < end) {
        int s0 = sp[i];
        float4 a0 = elp[s0];
        float4 f0 = *(const float4*)&feat[((size_t)p * Nn + s0) * 128 + lane * 4];
        float4 w0;
        float t;
        t = a0.x + er4.x; t = t > 0.f ? t : 0.2f * t; w0.x = __expf(t - mx.x);
        t = a0.y + er4.y; t = t > 0.f ? t : 0.2f * t; w0.y = __expf(t - mx.y);
        t = a0.z + er4.z; t = t > 0.f ? t : 0.2f * t; w0.z = __expf(t - mx.z);
        t = a0.w + er4.w; t = t > 0.f ? t : 0.2f * t; w0.w = __expf(t - mx.w);
        zs.x += w0.x; zs.y += w0.y; zs.z += w0.z; zs.w += w0.w;
        float c0 = head == 0 ? w0.x : head == 1 ? w0.y : head == 2 ? w0.z : w0.w;
        acc.x = fmaf(c0, f0.x, acc.x);
        acc.y = fmaf(c0, f0.y, acc.y);
        acc.z = fmaf(c0, f0.z, acc.z);
        acc.w = fmaf(c0, f0.w, acc.w);
    }
    float zsel = head == 0 ? zs.x : head == 1 ? zs.y : head == 2 ? zs.z : zs.w;
    float inv = 1.f / zsel;
    acc.x *= inv; acc.y *= inv; acc.z *= inv; acc.w *= inv;
    acc.x = acc.x > 0.f ? acc.x : expm1f(acc.x);
    acc.y = acc.y > 0.f ? acc.y : expm1f(acc.y);
    acc.z = acc.z > 0.f ? acc.z : expm1f(acc.z);
    acc.w = acc.w > 0.f ? acc.w : expm1f(acc.w);
    *(float4*)zp = acc;
}

// ---------------- softmax over meta-paths + combine -----------------------------------
__global__ void k_bsem(const float* __restrict__ wsem, float* __restrict__ bsem) {
    float w0 = wsem[0] / (float)Nn, w1 = wsem[1] / (float)Nn, w2 = wsem[2] / (float)Nn;
    float m = fmaxf(w0, fmaxf(w1, w2));
    float e0 = expf(w0 - m), e1 = expf(w1 - m), e2 = expf(w2 - m);
    float s = e0 + e1 + e2;
    bsem[0] = e0 / s; bsem[1] = e1 / s; bsem[2] = e2 / s;
}

__global__ void k_comb(const float* __restrict__ z, const float* __restrict__ bsem,
                       float* __restrict__ out) {
    long i = (long)blockIdx.x * 256 + threadIdx.x;
    if (i >= (long)Nn * 32) return;
    float b0 = bsem[0], b1 = bsem[1], b2 = bsem[2];
    const float4* z4 = (const float4*)z;
    float4 v0 = z4[i];
    float4 v1 = z4[(size_t)Nn * 32 + i];
    float4 v2 = z4[2 * (size_t)Nn * 32 + i];
    float4 o;
    o.x = b0 * v0.x + b1 * v1.x + b2 * v2.x;
    o.y = b0 * v0.y + b1 * v1.y + b2 * v2.y;
    o.z = b0 * v0.z + b1 * v1.z + b2 * v2.z;
    o.w = b0 * v0.w + b1 * v1.w + b2 * v2.w;
    ((float4*)out)[i] = o;
}

// ---------------- launch ----------------------------------------------------------------
extern "C" void kernel_launch(void* const* d_in, const int* in_sizes, int n_in,
                              void* d_out, int out_size) {
    const float* h      = (const float*)d_in[0];
    const float* cf     = (const float*)d_in[1];
    const float* fa_w1  = (const float*)d_in[2];
    const float* fa_b1  = (const float*)d_in[3];
    const float* fa_w2  = (const float*)d_in[4];
    const float* gat_W  = (const float*)d_in[5];
    const float* attn_l = (const float*)d_in[6];
    const float* attn_r = (const float*)d_in[7];
    const float* sa_w1  = (const float*)d_in[8];
    const float* sa_b1  = (const float*)d_in[9];
    const float* sa_w2  = (const float*)d_in[10];
    const int*   src    = (const int*)d_in[11];
    const int*   dst    = (const int*)d_in[12];
    float* out = (float*)d_out;

    float *px, *pfeat, *pz, *pel, *per, *pwsem, *pbsem;
    int *pdeg, *poff, *pcur, *pcsrc;
    __nv_bfloat16 *pbh, *pbl;
    cudaGetSymbolAddress((void**)&px, g_x);
    cudaGetSymbolAddress((void**)&pfeat, g_feat);
    cudaGetSymbolAddress((void**)&pz, g_z);
    cudaGetSymbolAddress((void**)&pel, g_el);
    cudaGetSymbolAddress((void**)&per, g_er);
    cudaGetSymbolAddress((void**)&pdeg, g_deg);
    cudaGetSymbolAddress((void**)&poff, g_off);
    cudaGetSymbolAddress((void**)&pcur, g_cur);
    cudaGetSymbolAddress((void**)&pcsrc, g_csrc);
    cudaGetSymbolAddress((void**)&pbh, g_bt_hi);
    cudaGetSymbolAddress((void**)&pbl, g_bt_lo);
    cudaGetSymbolAddress((void**)&pwsem, g_wsem);
    cudaGetSymbolAddress((void**)&pbsem, g_bsem);

    cudaFuncSetAttribute(k_gemm_feat, cudaFuncAttributeMaxDynamicSharedMemorySize, SMEM_TOT);
    cudaFuncSetAttribute(k_semgemm, cudaFuncAttributeMaxDynamicSharedMemorySize, SMEM_TOT);

    cudaMemsetAsync(pdeg, 0, sizeof(int) * (size_t)Pp * Nn, 0);
    cudaMemsetAsync(pwsem, 0, sizeof(float) * Pp, 0);

    k_wprep<<<(4 * 16384 + 255) / 256, 256>>>(gat_W, sa_w1, pbh, pbl);
    k_featatt<<<(Nn + 7) / 8, 256>>>(h, cf, fa_w1, fa_b1, fa_w2, px);

    dim3 ge((Ee + 255) / 256, Pp);
    k_count<<<ge, 256>>>(dst, pdeg);

    dim3 gg((Nn + 127) / 128, Pp);
    k_gemm_feat<<<gg, 256, SMEM_TOT>>>(px, pbh, pbl, attn_l, attn_r, pfeat, pel, per);

    k_scan<<<Pp, 1024>>>(pdeg, poff, pcur);
    k_scatter<<<ge, 256>>>(src, dst, pcur, pcsrc);

    dim3 gn((Nn + 7) / 8, Pp);
    k_gather<<<gn, 256>>>(pcsrc, poff, pel, per, pfeat, pz);

    k_semgemm<<<gg, 256, SMEM_TOT>>>(pz, pbh + 3 * 16384, pbl + 3 * 16384, sa_b1, sa_w2, pwsem);
    k_bsem<<<1, 1>>>(pwsem, pbsem);
    k_comb<<<(unsigned)(((long)Nn * 32 + 255) / 256), 256>>>(pz, pbsem, out);
}

// round 5
// speedup vs baseline: 1.1155x; 1.1155x over previous
#include <cuda_runtime.h>
#include <cuda_bf16.h>
#include <math.h>
#include <stdint.h>

#define Nn 50000
#define Ee 400000
#define Pp 3

// ---------------- scratch (device globals) --------------------------------------
__device__ __align__(16) float g_x[(size_t)Nn * 128];
__device__ __align__(16) float g_feat[(size_t)Pp * Nn * 128];
__device__ __align__(16) float g_z[(size_t)Pp * Nn * 128];
__device__ __align__(16) float g_el[(size_t)Pp * Nn * 4];
__device__ __align__(16) float g_er[(size_t)Pp * Nn * 4];
__device__ int g_deg[(size_t)Pp * Nn];
__device__ int g_off[(size_t)Pp * (Nn + 1)];
__device__ int g_cur[(size_t)Pp * Nn];
__device__ int g_csrc[(size_t)Pp * Ee];
__device__ __align__(16) __nv_bfloat16 g_bt_hi[4 * 128 * 128];  // [slot][n][k]
__device__ __align__(16) __nv_bfloat16 g_bt_lo[4 * 128 * 128];
__device__ float g_wsem[Pp];
__device__ float g_bsem[Pp];

// ---------------- smem layout: K-slabbed bf16 tiles (128 x 64 per slab) ----------
#define SROW 72                       // bf16 elements per padded row
#define TILEB (128 * SROW * 2)        // 18432 bytes
#define S_AUX0 0                      // 128 floats
#define S_AUX1 512                    // 128 floats
#define S_RED  1024                   // 8 floats
#define S_AH   2048
#define S_AL   (S_AH + TILEB)
#define S_BH   (S_AL + TILEB)
#define S_BL   (S_BH + TILEB)
#define SMEM_TOT (S_BL + TILEB)       // 75776
#define SDW 132                       // fp32 staging row stride (128x132x4 = 67584 <= 73728)

__device__ __forceinline__ void mma16816(float& d0, float& d1, float& d2, float& d3,
                                         uint32_t a0, uint32_t a1, uint32_t a2, uint32_t a3,
                                         uint32_t b0, uint32_t b1) {
    asm volatile(
        "mma.sync.aligned.m16n8k16.row.col.f32.bf16.bf16.f32 "
        "{%0,%1,%2,%3}, {%4,%5,%6,%7}, {%8,%9}, {%0,%1,%2,%3};"
        : "+f"(d0), "+f"(d1), "+f"(d2), "+f"(d3)
        : "r"(a0), "r"(a1), "r"(a2), "r"(a3), "r"(b0), "r"(b1));
}

__device__ __forceinline__ uint32_t bf2u(__nv_bfloat162 v) {
    return *reinterpret_cast<uint32_t*>(&v);
}

// K-slabbed mainloop: 2 slabs of K=64; per slab fill A (fp32 -> hi/lo bf16) and
// B (prebuilt hi/lo), then 3 precision passes x 4 k-steps of m16n8k16.
__device__ __forceinline__ void gemm_core(const float* __restrict__ Xsrc, int n0,
                                          const __nv_bfloat16* __restrict__ bth,
                                          const __nv_bfloat16* __restrict__ btl,
                                          char* smem, float d[2][8][4]) {
    int tid = threadIdx.x, lane = tid & 31, wid = tid >> 5;
    int warpM = wid & 3, warpN = wid >> 2;
    int arow = warpM * 32 + (lane >> 2);
    int acol = (lane & 3) * 2;
    int brow = warpN * 64 + (lane >> 2);
    int bcol = (lane & 3) * 2;

#pragma unroll
    for (int s = 0; s < 2; s++) {
        // A slab: rows 0..127, cols [64s, 64s+64) fp32 -> hi/lo bf16
#pragma unroll
        for (int it = 0; it < 8; it++) {
            int idx = it * 256 + tid;
            int row = idx >> 4;
            int c4 = idx & 15;
            int n = n0 + row;
            float4 v = make_float4(0.f, 0.f, 0.f, 0.f);
            if (n < Nn) v = *(const float4*)&Xsrc[(size_t)n * 128 + s * 64 + c4 * 4];
            __nv_bfloat162 h0 = __floats2bfloat162_rn(v.x, v.y);
            __nv_bfloat162 h1 = __floats2bfloat162_rn(v.z, v.w);
            float2 f0 = __bfloat1622float2(h0), f1 = __bfloat1622float2(h1);
            __nv_bfloat162 l0 = __floats2bfloat162_rn(v.x - f0.x, v.y - f0.y);
            __nv_bfloat162 l1 = __floats2bfloat162_rn(v.z - f1.x, v.w - f1.y);
            size_t off = ((size_t)row * SROW + c4 * 4) * 2;
            *(uint2*)(smem + S_AH + off) = make_uint2(bf2u(h0), bf2u(h1));
            *(uint2*)(smem + S_AL + off) = make_uint2(bf2u(l0), bf2u(l1));
        }
        // B slab: [n][k] slab cols
#pragma unroll
        for (int it = 0; it < 4; it++) {
            int idx = it * 256 + tid;
            int row = idx >> 3;
            int q = idx & 7;
            size_t off = ((size_t)row * SROW + q * 8) * 2;
            *(uint4*)(smem + S_BH + off) = *(const uint4*)(bth + (size_t)row * 128 + s * 64 + q * 8);
            *(uint4*)(smem + S_BL + off) = *(const uint4*)(btl + (size_t)row * 128 + s * 64 + q * 8);
        }
        __syncthreads();
#pragma unroll
        for (int pass = 0; pass < 3; pass++) {
            const char* pA = smem + ((pass == 2) ? S_AL : S_AH);
            const char* pB = smem + ((pass == 1) ? S_BL : S_BH);
#pragma unroll
            for (int ks = 0; ks < 4; ks++) {
                int k0 = ks * 16;
                uint32_t af[2][4];
#pragma unroll
                for (int mt = 0; mt < 2; mt++) {
                    const char* base = pA + ((size_t)(arow + mt * 16) * SROW + k0 + acol) * 2;
                    af[mt][0] = *(const uint32_t*)(base);
                    af[mt][1] = *(const uint32_t*)(base + 8 * SROW * 2);
                    af[mt][2] = *(const uint32_t*)(base + 16);
                    af[mt][3] = *(const uint32_t*)(base + 8 * SROW * 2 + 16);
                }
#pragma unroll
                for (int nt = 0; nt < 8; nt++) {
                    const char* base = pB + ((size_t)(brow + nt * 8) * SROW + k0 + bcol) * 2;
                    uint32_t b0 = *(const uint32_t*)(base);
                    uint32_t b1 = *(const uint32_t*)(base + 16);
#pragma unroll
                    for (int mt = 0; mt < 2; mt++)
                        mma16816(d[mt][nt][0], d[mt][nt][1], d[mt][nt][2], d[mt][nt][3],
                                 af[mt][0], af[mt][1], af[mt][2], af[mt][3], b0, b1);
                }
            }
        }
        __syncthreads();
    }
}

// stage accumulators to smem fp32 tile (row-major, stride SDW)
__device__ __forceinline__ void stage_d(float* sd, float d[2][8][4], int lane, int wid) {
    int warpM = wid & 3, warpN = wid >> 2;
    int rq = lane >> 2, cq = (lane & 3) * 2;
#pragma unroll
    for (int mt = 0; mt < 2; mt++) {
        int rl0 = warpM * 32 + mt * 16 + rq;
        int rl1 = rl0 + 8;
#pragma unroll
        for (int nt = 0; nt < 8; nt++) {
            int c = warpN * 64 + nt * 8 + cq;
            *(float2*)&sd[rl0 * SDW + c] = make_float2(d[mt][nt][0], d[mt][nt][1]);
            *(float2*)&sd[rl1 * SDW + c] = make_float2(d[mt][nt][2], d[mt][nt][3]);
        }
    }
}

// ---------------- projection GEMM + fused el/er -----------------------------------
__global__ void __launch_bounds__(256, 2) k_gemm_feat(
    const float* __restrict__ x, const __nv_bfloat16* __restrict__ bth,
    const __nv_bfloat16* __restrict__ btl, const float* __restrict__ al,
    const float* __restrict__ ar, float* __restrict__ feat, float* __restrict__ el,
    float* __restrict__ er) {
    extern __shared__ char smem[];
    int tid = threadIdx.x, lane = tid & 31, wid = tid >> 5;
    int p = blockIdx.y;
    int n0 = blockIdx.x * 128;
    float* sal = (float*)(smem + S_AUX0);
    float* sar = (float*)(smem + S_AUX1);
    if (tid < 128) { sal[tid] = al[p * 128 + tid]; sar[tid] = ar[p * 128 + tid]; }

    float d[2][8][4];
#pragma unroll
    for (int mt = 0; mt < 2; mt++)
#pragma unroll
        for (int nt = 0; nt < 8; nt++)
#pragma unroll
            for (int q = 0; q < 4; q++) d[mt][nt][q] = 0.f;

    gemm_core(x, n0, bth + (size_t)p * 16384, btl + (size_t)p * 16384, smem, d);

    float* sd = (float*)(smem + S_AH);
    stage_d(sd, d, lane, wid);
    __syncthreads();

    int row = tid >> 1, half = tid & 1;
    int n = n0 + row;
    if (n < Nn) {
        float sel[2] = {0.f, 0.f}, ser[2] = {0.f, 0.f};
        float4* o = (float4*)&feat[((size_t)p * Nn + n) * 128 + half * 64];
#pragma unroll
        for (int q = 0; q < 16; q++) {
            float4 v = *(float4*)&sd[row * SDW + half * 64 + q * 4];
            o[q] = v;
            int hb = q >> 3;
            int c = half * 64 + q * 4;
            sel[hb] = fmaf(v.x, sal[c + 0], sel[hb]);
            sel[hb] = fmaf(v.y, sal[c + 1], sel[hb]);
            sel[hb] = fmaf(v.z, sal[c + 2], sel[hb]);
            sel[hb] = fmaf(v.w, sal[c + 3], sel[hb]);
            ser[hb] = fmaf(v.x, sar[c + 0], ser[hb]);
            ser[hb] = fmaf(v.y, sar[c + 1], ser[hb]);
            ser[hb] = fmaf(v.z, sar[c + 2], ser[hb]);
            ser[hb] = fmaf(v.w, sar[c + 3], ser[hb]);
        }
        *(float2*)&el[((size_t)p * Nn + n) * 4 + half * 2] = make_float2(sel[0], sel[1]);
        *(float2*)&er[((size_t)p * Nn + n) * 4 + half * 2] = make_float2(ser[0], ser[1]);
    }
}

// ---------------- semantic GEMM + tanh/w2 reduce ------------------------------------
__global__ void __launch_bounds__(256, 2) k_semgemm(
    const float* __restrict__ z, const __nv_bfloat16* __restrict__ bth,
    const __nv_bfloat16* __restrict__ btl, const float* __restrict__ b1,
    const float* __restrict__ w2, float* __restrict__ wsem) {
    extern __shared__ char smem[];
    int tid = threadIdx.x, lane = tid & 31, wid = tid >> 5;
    int p = blockIdx.y;
    int n0 = blockIdx.x * 128;
    float* sb1 = (float*)(smem + S_AUX0);
    float* sw2 = (float*)(smem + S_AUX1);
    float* sred = (float*)(smem + S_RED);
    if (tid < 128) { sb1[tid] = b1[tid]; sw2[tid] = w2[tid]; }

    float d[2][8][4];
#pragma unroll
    for (int mt = 0; mt < 2; mt++)
#pragma unroll
        for (int nt = 0; nt < 8; nt++)
#pragma unroll
            for (int q = 0; q < 4; q++) d[mt][nt][q] = 0.f;

    gemm_core(z + (size_t)p * Nn * 128, n0, bth, btl, smem, d);

    float* sd = (float*)(smem + S_AH);
    stage_d(sd, d, lane, wid);
    __syncthreads();

    int row = tid >> 1, half = tid & 1;
    int n = n0 + row;
    float accv = 0.f;
    if (n < Nn) {
#pragma unroll
        for (int q = 0; q < 16; q++) {
            float4 v = *(float4*)&sd[row * SDW + half * 64 + q * 4];
            int c = half * 64 + q * 4;
            accv = fmaf(tanhf(v.x + sb1[c + 0]), sw2[c + 0], accv);
            accv = fmaf(tanhf(v.y + sb1[c + 1]), sw2[c + 1], accv);
            accv = fmaf(tanhf(v.z + sb1[c + 2]), sw2[c + 2], accv);
            accv = fmaf(tanhf(v.w + sb1[c + 3]), sw2[c + 3], accv);
        }
    }
#pragma unroll
    for (int o = 16; o; o >>= 1) accv += __shfl_xor_sync(0xffffffffu, accv, o);
    if (lane == 0) sred[wid] = accv;
    __syncthreads();
    if (tid == 0) {
        float s = 0.f;
#pragma unroll
        for (int i = 0; i < 8; i++) s += sred[i];
        atomicAdd(&wsem[p], s);
    }
}

// ---------------- feature attention: warp per node ----------------------------------
__global__ void k_featatt(const float* __restrict__ h, const float* __restrict__ cf,
                          const float* __restrict__ w1, const float* __restrict__ b1,
                          const float* __restrict__ w2, float* __restrict__ x) {
    __shared__ float sw1[42 * 16];
    __shared__ float sb1[16], sw2[16];
    __shared__ float sf[8][840];
    __shared__ float ss[8][20];
    int tid = threadIdx.x, wid = tid >> 5, lane = tid & 31;
    for (int i = tid; i < 672; i += 256) sw1[i] = w1[i];
    if (tid < 16) { sb1[tid] = b1[tid]; sw2[tid] = w2[tid]; }
    __syncthreads();
    int n = blockIdx.x * 8 + wid;
    if (n >= Nn) return;

    const float* fr = cf + (size_t)n * 840;
    float* myf = sf[wid];
    for (int i = lane; i < 840; i += 32) myf[i] = fr[i];
    __syncwarp();

    int k = lane & 15;
    for (int j0 = 0; j0 < 20; j0 += 2) {
        int j = j0 + (lane >> 4);
        const float* fj = myf + j * 42;
        float acc = sb1[k];
#pragma unroll
        for (int i = 0; i < 42; i++) acc = fmaf(fj[i], sw1[i * 16 + k], acc);
        float v = tanhf(acc) * sw2[k];
#pragma unroll
        for (int off = 8; off; off >>= 1) v += __shfl_down_sync(0xffffffffu, v, off);
        if (k == 0) ss[wid][j] = v;
    }
    __syncwarp();

    float sc = (lane < 20) ? ss[wid][lane] : -INFINITY;
    float mx = sc;
#pragma unroll
    for (int off = 16; off; off >>= 1) mx = fmaxf(mx, __shfl_xor_sync(0xffffffffu, mx, off));
    float ex = (lane < 20) ? expf(sc - mx) : 0.f;
    float sm = ex;
#pragma unroll
    for (int off = 16; off; off >>= 1) sm += __shfl_xor_sync(0xffffffffu, sm, off);
    float beta = ex / sm;

    float a0 = 0.f, a1 = 0.f;
    for (int j = 0; j < 20; j++) {
        float bj = __shfl_sync(0xffffffffu, beta, j);
        a0 = fmaf(bj, myf[j * 42 + lane], a0);
        if (lane < 10) a1 = fmaf(bj, myf[j * 42 + 32 + lane], a1);
    }
    float* xr = x + (size_t)n * 128;
    const float* hr = h + (size_t)n * 86;
    for (int i = lane; i < 86; i += 32) xr[i] = hr[i];
    xr[86 + lane] = a0;
    if (lane < 10) xr[118 + lane] = a1;
}

// ---------------- weight prep: transpose + bf16 hi/lo split --------------------------
__global__ void k_wprep(const float* __restrict__ gatW, const float* __restrict__ saw1,
                        __nv_bfloat16* __restrict__ bh, __nv_bfloat16* __restrict__ bl) {
    int idx = blockIdx.x * 256 + threadIdx.x;
    if (idx >= 4 * 16384) return;
    int slot = idx >> 14, rem = idx & 16383;
    int nIdx = rem >> 7, kIdx = rem & 127;
    float v = (slot < 3) ? gatW[slot * 16384 + kIdx * 128 + nIdx] : saw1[kIdx * 128 + nIdx];
    __nv_bfloat16 hh = __float2bfloat16(v);
    bh[idx] = hh;
    bl[idx] = __float2bfloat16(v - __bfloat162float(hh));
}

// ---------------- CSR build -----------------------------------------------------------
__global__ void k_count(const int* __restrict__ dst, int* __restrict__ deg) {
    int p = blockIdx.y;
    int e = blockIdx.x * 256 + threadIdx.x;
    if (e >= Ee) return;
    atomicAdd(&deg[(size_t)p * Nn + dst[(size_t)p * Ee + e]], 1);
}

__global__ void k_scan(const int* __restrict__ deg, int* __restrict__ off,
                       int* __restrict__ cur) {
    int p = blockIdx.x;
    int tid = threadIdx.x, lane = tid & 31, wid = tid >> 5;
    __shared__ int wsum[32];
    __shared__ int carry;
    if (tid == 0) carry = 0;
    __syncthreads();
    for (int base = 0; base < Nn; base += 1024) {
        int i = base + tid;
        int v = (i < Nn) ? deg[(size_t)p * Nn + i] : 0;
        int xv = v;
#pragma unroll
        for (int o = 1; o < 32; o <<= 1) {
            int t = __shfl_up_sync(0xffffffffu, xv, o);
            if (lane >= o) xv += t;
        }
        if (lane == 31) wsum[wid] = xv;
        __syncthreads();
        if (wid == 0) {
            int y = wsum[lane];
#pragma unroll
            for (int o = 1; o < 32; o <<= 1) {
                int t = __shfl_up_sync(0xffffffffu, y, o);
                if (lane >= o) y += t;
            }
            wsum[lane] = y;
        }
        __syncthreads();
        int wpre = (wid == 0) ? 0 : wsum[wid - 1];
        int excl = carry + wpre + xv - v;
        if (i < Nn) {
            off[(size_t)p * (Nn + 1) + i] = excl;
            cur[(size_t)p * Nn + i] = excl;
        }
        __syncthreads();
        if (tid == 1023) carry = excl + v;
        __syncthreads();
    }
    if (tid == 0) off[(size_t)p * (Nn + 1) + Nn] = carry;
}

__global__ void k_scatter(const int* __restrict__ src, const int* __restrict__ dst,
                          int* __restrict__ cur, int* __restrict__ csrc) {
    int p = blockIdx.y;
    int e = blockIdx.x * 256 + threadIdx.x;
    if (e >= Ee) return;
    int d = dst[(size_t)p * Ee + e];
    int pos = atomicAdd(&cur[(size_t)p * Nn + d], 1);
    csrc[(size_t)p * Ee + pos] = src[(size_t)p * Ee + e];
}

// ---------------- gather aggregation: warp per (p, dst) -------------------------------
__global__ void k_gather(const int* __restrict__ csrc, const int* __restrict__ off,
                         const float* __restrict__ el, const float* __restrict__ er,
                         const float* __restrict__ feat, float* __restrict__ z) {
    int p = blockIdx.y;
    int tid = threadIdx.x, wid = tid >> 5, lane = tid & 31;
    int n = blockIdx.x * 8 + wid;
    if (n >= Nn) return;
    long r = (long)p * Nn + n;
    int start = off[(size_t)p * (Nn + 1) + n];
    int end = off[(size_t)p * (Nn + 1) + n + 1];
    float* zp = &z[r * 128 + lane * 4];
    if (start == end) {
        *(float4*)zp = make_float4(0.f, 0.f, 0.f, 0.f);
        return;
    }
    const int* sp = csrc + (size_t)p * Ee;
    const float4* elp = (const float4*)el + (size_t)p * Nn;
    float4 er4 = ((const float4*)er)[r];

    float4 mx = make_float4(-INFINITY, -INFINITY, -INFINITY, -INFINITY);
    for (int i = start + lane; i < end; i += 32) {
        float4 a = elp[sp[i]];
        float vx = a.x + er4.x; vx = vx > 0.f ? vx : 0.2f * vx;
        float vy = a.y + er4.y; vy = vy > 0.f ? vy : 0.2f * vy;
        float vz = a.z + er4.z; vz = vz > 0.f ? vz : 0.2f * vz;
        float vw = a.w + er4.w; vw = vw > 0.f ? vw : 0.2f * vw;
        mx.x = fmaxf(mx.x, vx); mx.y = fmaxf(mx.y, vy);
        mx.z = fmaxf(mx.z, vz); mx.w = fmaxf(mx.w, vw);
    }
#pragma unroll
    for (int o = 16; o; o >>= 1) {
        mx.x = fmaxf(mx.x, __shfl_xor_sync(0xffffffffu, mx.x, o));
        mx.y = fmaxf(mx.y, __shfl_xor_sync(0xffffffffu, mx.y, o));
        mx.z = fmaxf(mx.z, __shfl_xor_sync(0xffffffffu, mx.z, o));
        mx.w = fmaxf(mx.w, __shfl_xor_sync(0xffffffffu, mx.w, o));
    }

    int head = lane >> 3;
    float4 acc = make_float4(0.f, 0.f, 0.f, 0.f);
    float4 zs = make_float4(0.f, 0.f, 0.f, 0.f);
    int i = start;
    for (; i + 1 < end; i += 2) {
        int s0 = sp[i], s1 = sp[i + 1];
        float4 a0 = elp[s0], a1 = elp[s1];
        float4 f0 = *(const float4*)&feat[((size_t)p * Nn + s0) * 128 + lane * 4];
        float4 f1 = *(const float4*)&feat[((size_t)p * Nn + s1) * 128 + lane * 4];
        float4 w0, w1;
        float t;
        t = a0.x + er4.x; t = t > 0.f ? t : 0.2f * t; w0.x = __expf(t - mx.x);
        t = a0.y + er4.y; t = t > 0.f ? t : 0.2f * t; w0.y = __expf(t - mx.y);
        t = a0.z + er4.z; t = t > 0.f ? t : 0.2f * t; w0.z = __expf(t - mx.z);
        t = a0.w + er4.w; t = t > 0.f ? t : 0.2f * t; w0.w = __expf(t - mx.w);
        t = a1.x + er4.x; t = t > 0.f ? t : 0.2f * t; w1.x = __expf(t - mx.x);
        t = a1.y + er4.y; t = t > 0.f ? t : 0.2f * t; w1.y = __expf(t - mx.y);
        t = a1.z + er4.z; t = t > 0.f ? t : 0.2f * t; w1.z = __expf(t - mx.z);
        t = a1.w + er4.w; t = t > 0.f ? t : 0.2f * t; w1.w = __expf(t - mx.w);
        zs.x += w0.x + w1.x; zs.y += w0.y + w1.y;
        zs.z += w0.z + w1.z; zs.w += w0.w + w1.w;
        float c0 = head == 0 ? w0.x : head == 1 ? w0.y : head == 2 ? w0.z : w0.w;
        float c1 = head == 0 ? w1.x : head == 1 ? w1.y : head == 2 ? w1.z : w1.w;
        acc.x = fmaf(c0, f0.x, acc.x); acc.x = fmaf(c1, f1.x, acc.x);
        acc.y = fmaf(c0, f0.y, acc.y); acc.y = fmaf(c1, f1.y, acc.y);
        acc.z = fmaf(c0, f0.z, acc.z); acc.z = fmaf(c1, f1.z, acc.z);
        acc.w = fmaf(c0, f0.w, acc.w); acc.w = fmaf(c1, f1.w, acc.w);
    }
    if (i < end) {
        int s0 = sp[i];
        float4 a0 = elp[s0];
        float4 f0 = *(const float4*)&feat[((size_t)p * Nn + s0) * 128 + lane * 4];
        float4 w0;
        float t;
        t = a0.x + er4.x; t = t > 0.f ? t : 0.2f * t; w0.x = __expf(t - mx.x);
        t = a0.y + er4.y; t = t > 0.f ? t : 0.2f * t; w0.y = __expf(t - mx.y);
        t = a0.z + er4.z; t = t > 0.f ? t : 0.2f * t; w0.z = __expf(t - mx.z);
        t = a0.w + er4.w; t = t > 0.f ? t : 0.2f * t; w0.w = __expf(t - mx.w);
        zs.x += w0.x; zs.y += w0.y; zs.z += w0.z; zs.w += w0.w;
        float c0 = head == 0 ? w0.x : head == 1 ? w0.y : head == 2 ? w0.z : w0.w;
        acc.x = fmaf(c0, f0.x, acc.x);
        acc.y = fmaf(c0, f0.y, acc.y);
        acc.z = fmaf(c0, f0.z, acc.z);
        acc.w = fmaf(c0, f0.w, acc.w);
    }
    float zsel = head == 0 ? zs.x : head == 1 ? zs.y : head == 2 ? zs.z : zs.w;
    float inv = 1.f / zsel;
    acc.x *= inv; acc.y *= inv; acc.z *= inv; acc.w *= inv;
    acc.x = acc.x > 0.f ? acc.x : expm1f(acc.x);
    acc.y = acc.y > 0.f ? acc.y : expm1f(acc.y);
    acc.z = acc.z > 0.f ? acc.z : expm1f(acc.z);
    acc.w = acc.w > 0.f ? acc.w : expm1f(acc.w);
    *(float4*)zp = acc;
}

// ---------------- softmax over meta-paths + combine -----------------------------------
__global__ void k_bsem(const float* __restrict__ wsem, float* __restrict__ bsem) {
    float w0 = wsem[0] / (float)Nn, w1 = wsem[1] / (float)Nn, w2 = wsem[2] / (float)Nn;
    float m = fmaxf(w0, fmaxf(w1, w2));
    float e0 = expf(w0 - m), e1 = expf(w1 - m), e2 = expf(w2 - m);
    float s = e0 + e1 + e2;
    bsem[0] = e0 / s; bsem[1] = e1 / s; bsem[2] = e2 / s;
}

__global__ void k_comb(const float* __restrict__ z, const float* __restrict__ bsem,
                       float* __restrict__ out) {
    long i = (long)blockIdx.x * 256 + threadIdx.x;
    if (i >= (long)Nn * 32) return;
    float b0 = bsem[0], b1 = bsem[1], b2 = bsem[2];
    const float4* z4 = (const float4*)z;
    float4 v0 = z4[i];
    float4 v1 = z4[(size_t)Nn * 32 + i];
    float4 v2 = z4[2 * (size_t)Nn * 32 + i];
    float4 o;
    o.x = b0 * v0.x + b1 * v1.x + b2 * v2.x;
    o.y = b0 * v0.y + b1 * v1.y + b2 * v2.y;
    o.z = b0 * v0.z + b1 * v1.z + b2 * v2.z;
    o.w = b0 * v0.w + b1 * v1.w + b2 * v2.w;
    ((float4*)out)[i] = o;
}

// ---------------- launch ----------------------------------------------------------------
extern "C" void kernel_launch(void* const* d_in, const int* in_sizes, int n_in,
                              void* d_out, int out_size) {
    const float* h      = (const float*)d_in[0];
    const float* cf     = (const float*)d_in[1];
    const float* fa_w1  = (const float*)d_in[2];
    const float* fa_b1  = (const float*)d_in[3];
    const float* fa_w2  = (const float*)d_in[4];
    const float* gat_W  = (const float*)d_in[5];
    const float* attn_l = (const float*)d_in[6];
    const float* attn_r = (const float*)d_in[7];
    const float* sa_w1  = (const float*)d_in[8];
    const float* sa_b1  = (const float*)d_in[9];
    const float* sa_w2  = (const float*)d_in[10];
    const int*   src    = (const int*)d_in[11];
    const int*   dst    = (const int*)d_in[12];
    float* out = (float*)d_out;

    float *px, *pfeat, *pz, *pel, *per, *pwsem, *pbsem;
    int *pdeg, *poff, *pcur, *pcsrc;
    __nv_bfloat16 *pbh, *pbl;
    cudaGetSymbolAddress((void**)&px, g_x);
    cudaGetSymbolAddress((void**)&pfeat, g_feat);
    cudaGetSymbolAddress((void**)&pz, g_z);
    cudaGetSymbolAddress((void**)&pel, g_el);
    cudaGetSymbolAddress((void**)&per, g_er);
    cudaGetSymbolAddress((void**)&pdeg, g_deg);
    cudaGetSymbolAddress((void**)&poff, g_off);
    cudaGetSymbolAddress((void**)&pcur, g_cur);
    cudaGetSymbolAddress((void**)&pcsrc, g_csrc);
    cudaGetSymbolAddress((void**)&pbh, g_bt_hi);
    cudaGetSymbolAddress((void**)&pbl, g_bt_lo);
    cudaGetSymbolAddress((void**)&pwsem, g_wsem);
    cudaGetSymbolAddress((void**)&pbsem, g_bsem);

    cudaFuncSetAttribute(k_gemm_feat, cudaFuncAttributeMaxDynamicSharedMemorySize, SMEM_TOT);
    cudaFuncSetAttribute(k_semgemm, cudaFuncAttributeMaxDynamicSharedMemorySize, SMEM_TOT);

    cudaMemsetAsync(pdeg, 0, sizeof(int) * (size_t)Pp * Nn, 0);
    cudaMemsetAsync(pwsem, 0, sizeof(float) * Pp, 0);

    k_wprep<<<(4 * 16384 + 255) / 256, 256>>>(gat_W, sa_w1, pbh, pbl);
    k_featatt<<<(Nn + 7) / 8, 256>>>(h, cf, fa_w1, fa_b1, fa_w2, px);

    dim3 ge((Ee + 255) / 256, Pp);
    k_count<<<ge, 256>>>(dst, pdeg);

    dim3 gg((Nn + 127) / 128, Pp);
    k_gemm_feat<<<gg, 256, SMEM_TOT>>>(px, pbh, pbl, attn_l, attn_r, pfeat, pel, per);

    k_scan<<<Pp, 1024>>>(pdeg, poff, pcur);
    k_scatter<<<ge, 256>>>(src, dst, pcur, pcsrc);

    dim3 gn((Nn + 7) / 8, Pp);
    k_gather<<<gn, 256>>>(pcsrc, poff, pel, per, pfeat, pz);

    k_semgemm<<<gg, 256, SMEM_TOT>>>(pz, pbh + 3 * 16384, pbl + 3 * 16384, sa_b1, sa_w2, pwsem);
    k_bsem<<<1, 1>>>(pwsem, pbsem);
    k_comb<<<(unsigned)(((long)Nn * 32 + 255) / 256), 256>>>(pz, pbsem, out);
}

// round 6
// speedup vs baseline: 1.1629x; 1.0426x over previous
#include <cuda_runtime.h>
#include <cuda_bf16.h>
#include <math.h>
#include <stdint.h>

#define Nn 50000
#define Ee 400000
#define Pp 3

// ---------------- scratch (device globals) --------------------------------------
__device__ __align__(16) float g_x[(size_t)Nn * 128];
__device__ __align__(16) float g_feat[(size_t)Pp * Nn * 128];
__device__ __align__(16) float g_z[(size_t)Pp * Nn * 128];
__device__ __align__(16) float g_el[(size_t)Pp * Nn * 4];
__device__ __align__(16) float g_er[(size_t)Pp * Nn * 4];
__device__ int g_deg[(size_t)Pp * Nn];
__device__ int g_off[(size_t)Pp * (Nn + 1)];
__device__ int g_cur[(size_t)Pp * Nn];
__device__ int g_csrc[(size_t)Pp * Ee];
__device__ __align__(16) __nv_bfloat16 g_bt_hi[4 * 128 * 128];  // [slot][n][k]
__device__ __align__(16) __nv_bfloat16 g_bt_lo[4 * 128 * 128];
__device__ float g_wsem[Pp];
__device__ float g_bsem[Pp];

// ---------------- smem layout: K-slabbed bf16 tiles (128 x 64 per slab) ----------
#define SROW 72
#define TILEB (128 * SROW * 2)        // 18432
#define S_AUX0 0
#define S_AUX1 512
#define S_RED  1024
#define S_AH   2048
#define S_AL   (S_AH + TILEB)
#define S_BH   (S_AL + TILEB)
#define S_BL   (S_BH + TILEB)
#define SMEM_TOT (S_BL + TILEB)       // 75776
#define SDW 132

__device__ __forceinline__ void mma16816(float& d0, float& d1, float& d2, float& d3,
                                         uint32_t a0, uint32_t a1, uint32_t a2, uint32_t a3,
                                         uint32_t b0, uint32_t b1) {
    asm volatile(
        "mma.sync.aligned.m16n8k16.row.col.f32.bf16.bf16.f32 "
        "{%0,%1,%2,%3}, {%4,%5,%6,%7}, {%8,%9}, {%0,%1,%2,%3};"
        : "+f"(d0), "+f"(d1), "+f"(d2), "+f"(d3)
        : "r"(a0), "r"(a1), "r"(a2), "r"(a3), "r"(b0), "r"(b1));
}

__device__ __forceinline__ void ldsm4(uint32_t& r0, uint32_t& r1, uint32_t& r2,
                                      uint32_t& r3, uint32_t addr) {
    asm volatile("ldmatrix.sync.aligned.m8n8.x4.shared.b16 {%0,%1,%2,%3}, [%4];"
                 : "=r"(r0), "=r"(r1), "=r"(r2), "=r"(r3) : "r"(addr));
}

__device__ __forceinline__ uint32_t bf2u(__nv_bfloat162 v) {
    return *reinterpret_cast<uint32_t*>(&v);
}

// K-slabbed mainloop with ldmatrix fragments and pass-reordered reuse.
__device__ __forceinline__ void gemm_core(const float* __restrict__ Xsrc, int n0,
                                          const __nv_bfloat16* __restrict__ bth,
                                          const __nv_bfloat16* __restrict__ btl,
                                          char* smem, float d[2][8][4]) {
    int tid = threadIdx.x, lane = tid & 31, wid = tid >> 5;
    int warpM = wid & 3, warpN = wid >> 2;
    uint32_t smem_s = (uint32_t)__cvta_generic_to_shared(smem);

    // per-lane ldmatrix base addresses
    int grp = lane >> 3, lr = lane & 7;
    // A: r0=(mlo,klo) r1=(mhi,klo) r2=(mlo,khi) r3=(mhi,khi)
    uint32_t aA = smem_s + S_AH +
        (uint32_t)(((warpM * 32 + lr + (grp & 1) * 8) * SROW + (grp >> 1) * 8) * 2);
    // B: r0=(nlo,klo) r1=(nlo,khi) r2=(nhi,klo) r3=(nhi,khi)
    uint32_t aB = smem_s + S_BH +
        (uint32_t)(((warpN * 64 + lr + (grp >> 1) * 8) * SROW + (grp & 1) * 8) * 2);
    const uint32_t ALO = S_AL - S_AH, BLO = S_BL - S_BH;
    const uint32_t MT = 16 * SROW * 2;   // row-block stride

#pragma unroll
    for (int s = 0; s < 2; s++) {
        // A slab fill: fp32 -> hi/lo bf16
#pragma unroll
        for (int it = 0; it < 8; it++) {
            int idx = it * 256 + tid;
            int row = idx >> 4;
            int c4 = idx & 15;
            int n = n0 + row;
            float4 v = make_float4(0.f, 0.f, 0.f, 0.f);
            if (n < Nn) v = *(const float4*)&Xsrc[(size_t)n * 128 + s * 64 + c4 * 4];
            __nv_bfloat162 h0 = __floats2bfloat162_rn(v.x, v.y);
            __nv_bfloat162 h1 = __floats2bfloat162_rn(v.z, v.w);
            float2 f0 = __bfloat1622float2(h0), f1 = __bfloat1622float2(h1);
            __nv_bfloat162 l0 = __floats2bfloat162_rn(v.x - f0.x, v.y - f0.y);
            __nv_bfloat162 l1 = __floats2bfloat162_rn(v.z - f1.x, v.w - f1.y);
            size_t off = ((size_t)row * SROW + c4 * 4) * 2;
            *(uint2*)(smem + S_AH + off) = make_uint2(bf2u(h0), bf2u(h1));
            *(uint2*)(smem + S_AL + off) = make_uint2(bf2u(l0), bf2u(l1));
        }
        // B slab fill
#pragma unroll
        for (int it = 0; it < 4; it++) {
            int idx = it * 256 + tid;
            int row = idx >> 3;
            int q = idx & 7;
            size_t off = ((size_t)row * SROW + q * 8) * 2;
            *(uint4*)(smem + S_BH + off) = *(const uint4*)(bth + (size_t)row * 128 + s * 64 + q * 8);
            *(uint4*)(smem + S_BL + off) = *(const uint4*)(btl + (size_t)row * 128 + s * 64 + q * 8);
        }
        __syncthreads();

#pragma unroll
        for (int ks = 0; ks < 4; ks++) {
            uint32_t kb = (uint32_t)(ks * 16 * 2);
            uint32_t ah[2][4], al[2][4], bb[4][4];
#pragma unroll
            for (int mt = 0; mt < 2; mt++) {
                ldsm4(ah[mt][0], ah[mt][1], ah[mt][2], ah[mt][3], aA + mt * MT + kb);
                ldsm4(al[mt][0], al[mt][1], al[mt][2], al[mt][3], aA + ALO + mt * MT + kb);
            }
#pragma unroll
            for (int np = 0; np < 4; np++)
                ldsm4(bb[np][0], bb[np][1], bb[np][2], bb[np][3], aB + np * MT + kb);
            // Ah x Bh
#pragma unroll
            for (int np = 0; np < 4; np++)
#pragma unroll
                for (int mt = 0; mt < 2; mt++) {
                    mma16816(d[mt][2 * np][0], d[mt][2 * np][1], d[mt][2 * np][2], d[mt][2 * np][3],
                             ah[mt][0], ah[mt][1], ah[mt][2], ah[mt][3], bb[np][0], bb[np][1]);
                    mma16816(d[mt][2 * np + 1][0], d[mt][2 * np + 1][1], d[mt][2 * np + 1][2], d[mt][2 * np + 1][3],
                             ah[mt][0], ah[mt][1], ah[mt][2], ah[mt][3], bb[np][2], bb[np][3]);
                }
            // Al x Bh
#pragma unroll
            for (int np = 0; np < 4; np++)
#pragma unroll
                for (int mt = 0; mt < 2; mt++) {
                    mma16816(d[mt][2 * np][0], d[mt][2 * np][1], d[mt][2 * np][2], d[mt][2 * np][3],
                             al[mt][0], al[mt][1], al[mt][2], al[mt][3], bb[np][0], bb[np][1]);
                    mma16816(d[mt][2 * np + 1][0], d[mt][2 * np + 1][1], d[mt][2 * np + 1][2], d[mt][2 * np + 1][3],
                             al[mt][0], al[mt][1], al[mt][2], al[mt][3], bb[np][2], bb[np][3]);
                }
            // Bl, then Ah x Bl
#pragma unroll
            for (int np = 0; np < 4; np++)
                ldsm4(bb[np][0], bb[np][1], bb[np][2], bb[np][3], aB + BLO + np * MT + kb);
#pragma unroll
            for (int np = 0; np < 4; np++)
#pragma unroll
                for (int mt = 0; mt < 2; mt++) {
                    mma16816(d[mt][2 * np][0], d[mt][2 * np][1], d[mt][2 * np][2], d[mt][2 * np][3],
                             ah[mt][0], ah[mt][1], ah[mt][2], ah[mt][3], bb[np][0], bb[np][1]);
                    mma16816(d[mt][2 * np + 1][0], d[mt][2 * np + 1][1], d[mt][2 * np + 1][2], d[mt][2 * np + 1][3],
                             ah[mt][0], ah[mt][1], ah[mt][2], ah[mt][3], bb[np][2], bb[np][3]);
                }
        }
        __syncthreads();
    }
}

// stage accumulators to smem fp32 tile
__device__ __forceinline__ void stage_d(float* sd, float d[2][8][4], int lane, int wid) {
    int warpM = wid & 3, warpN = wid >> 2;
    int rq = lane >> 2, cq = (lane & 3) * 2;
#pragma unroll
    for (int mt = 0; mt < 2; mt++) {
        int rl0 = warpM * 32 + mt * 16 + rq;
        int rl1 = rl0 + 8;
#pragma unroll
        for (int nt = 0; nt < 8; nt++) {
            int c = warpN * 64 + nt * 8 + cq;
            *(float2*)&sd[rl0 * SDW + c] = make_float2(d[mt][nt][0], d[mt][nt][1]);
            *(float2*)&sd[rl1 * SDW + c] = make_float2(d[mt][nt][2], d[mt][nt][3]);
        }
    }
}

// ---------------- projection GEMM + fused el/er -----------------------------------
__global__ void __launch_bounds__(256, 2) k_gemm_feat(
    const float* __restrict__ x, const __nv_bfloat16* __restrict__ bth,
    const __nv_bfloat16* __restrict__ btl, const float* __restrict__ al,
    const float* __restrict__ ar, float* __restrict__ feat, float* __restrict__ el,
    float* __restrict__ er) {
    extern __shared__ char smem[];
    int tid = threadIdx.x, lane = tid & 31, wid = tid >> 5;
    int p = blockIdx.y;
    int n0 = blockIdx.x * 128;
    float* sal = (float*)(smem + S_AUX0);
    float* sar = (float*)(smem + S_AUX1);
    if (tid < 128) { sal[tid] = al[p * 128 + tid]; sar[tid] = ar[p * 128 + tid]; }

    float d[2][8][4];
#pragma unroll
    for (int mt = 0; mt < 2; mt++)
#pragma unroll
        for (int nt = 0; nt < 8; nt++)
#pragma unroll
            for (int q = 0; q < 4; q++) d[mt][nt][q] = 0.f;

    gemm_core(x, n0, bth + (size_t)p * 16384, btl + (size_t)p * 16384, smem, d);

    float* sd = (float*)(smem + S_AH);
    stage_d(sd, d, lane, wid);
    __syncthreads();

    int row = tid >> 1, half = tid & 1;
    int n = n0 + row;
    if (n < Nn) {
        float sel[2] = {0.f, 0.f}, ser[2] = {0.f, 0.f};
        float4* o = (float4*)&feat[((size_t)p * Nn + n) * 128 + half * 64];
#pragma unroll
        for (int q = 0; q < 16; q++) {
            float4 v = *(float4*)&sd[row * SDW + half * 64 + q * 4];
            o[q] = v;
            int hb = q >> 3;
            int c = half * 64 + q * 4;
            sel[hb] = fmaf(v.x, sal[c + 0], sel[hb]);
            sel[hb] = fmaf(v.y, sal[c + 1], sel[hb]);
            sel[hb] = fmaf(v.z, sal[c + 2], sel[hb]);
            sel[hb] = fmaf(v.w, sal[c + 3], sel[hb]);
            ser[hb] = fmaf(v.x, sar[c + 0], ser[hb]);
            ser[hb] = fmaf(v.y, sar[c + 1], ser[hb]);
            ser[hb] = fmaf(v.z, sar[c + 2], ser[hb]);
            ser[hb] = fmaf(v.w, sar[c + 3], ser[hb]);
        }
        *(float2*)&el[((size_t)p * Nn + n) * 4 + half * 2] = make_float2(sel[0], sel[1]);
        *(float2*)&er[((size_t)p * Nn + n) * 4 + half * 2] = make_float2(ser[0], ser[1]);
    }
}

// ---------------- semantic GEMM + tanh/w2 reduce ------------------------------------
__global__ void __launch_bounds__(256, 2) k_semgemm(
    const float* __restrict__ z, const __nv_bfloat16* __restrict__ bth,
    const __nv_bfloat16* __restrict__ btl, const float* __restrict__ b1,
    const float* __restrict__ w2, float* __restrict__ wsem) {
    extern __shared__ char smem[];
    int tid = threadIdx.x, lane = tid & 31, wid = tid >> 5;
    int p = blockIdx.y;
    int n0 = blockIdx.x * 128;
    float* sb1 = (float*)(smem + S_AUX0);
    float* sw2 = (float*)(smem + S_AUX1);
    float* sred = (float*)(smem + S_RED);
    if (tid < 128) { sb1[tid] = b1[tid]; sw2[tid] = w2[tid]; }

    float d[2][8][4];
#pragma unroll
    for (int mt = 0; mt < 2; mt++)
#pragma unroll
        for (int nt = 0; nt < 8; nt++)
#pragma unroll
            for (int q = 0; q < 4; q++) d[mt][nt][q] = 0.f;

    gemm_core(z + (size_t)p * Nn * 128, n0, bth, btl, smem, d);

    float* sd = (float*)(smem + S_AH);
    stage_d(sd, d, lane, wid);
    __syncthreads();

    int row = tid >> 1, half = tid & 1;
    int n = n0 + row;
    float accv = 0.f;
    if (n < Nn) {
#pragma unroll
        for (int q = 0; q < 16; q++) {
            float4 v = *(float4*)&sd[row * SDW + half * 64 + q * 4];
            int c = half * 64 + q * 4;
            accv = fmaf(tanhf(v.x + sb1[c + 0]), sw2[c + 0], accv);
            accv = fmaf(tanhf(v.y + sb1[c + 1]), sw2[c + 1], accv);
            accv = fmaf(tanhf(v.z + sb1[c + 2]), sw2[c + 2], accv);
            accv = fmaf(tanhf(v.w + sb1[c + 3]), sw2[c + 3], accv);
        }
    }
#pragma unroll
    for (int o = 16; o; o >>= 1) accv += __shfl_xor_sync(0xffffffffu, accv, o);
    if (lane == 0) sred[wid] = accv;
    __syncthreads();
    if (tid == 0) {
        float s = 0.f;
#pragma unroll
        for (int i = 0; i < 8; i++) s += sred[i];
        atomicAdd(&wsem[p], s);
    }
}

// ---------------- feature attention: warp per node ----------------------------------
__global__ void k_featatt(const float* __restrict__ h, const float* __restrict__ cf,
                          const float* __restrict__ w1, const float* __restrict__ b1,
                          const float* __restrict__ w2, float* __restrict__ x) {
    __shared__ float sw1[42 * 16];
    __shared__ float sb1[16], sw2[16];
    __shared__ float sf[8][840];
    __shared__ float ss[8][20];
    int tid = threadIdx.x, wid = tid >> 5, lane = tid & 31;
    for (int i = tid; i < 672; i += 256) sw1[i] = w1[i];
    if (tid < 16) { sb1[tid] = b1[tid]; sw2[tid] = w2[tid]; }
    __syncthreads();
    int n = blockIdx.x * 8 + wid;
    if (n >= Nn) return;

    const float* fr = cf + (size_t)n * 840;
    float* myf = sf[wid];
    for (int i = lane; i < 840; i += 32) myf[i] = fr[i];
    __syncwarp();

    int k = lane & 15;
    for (int j0 = 0; j0 < 20; j0 += 2) {
        int j = j0 + (lane >> 4);
        const float* fj = myf + j * 42;
        float acc = sb1[k];
#pragma unroll
        for (int i = 0; i < 42; i++) acc = fmaf(fj[i], sw1[i * 16 + k], acc);
        float v = tanhf(acc) * sw2[k];
#pragma unroll
        for (int off = 8; off; off >>= 1) v += __shfl_down_sync(0xffffffffu, v, off);
        if (k == 0) ss[wid][j] = v;
    }
    __syncwarp();

    float sc = (lane < 20) ? ss[wid][lane] : -INFINITY;
    float mx = sc;
#pragma unroll
    for (int off = 16; off; off >>= 1) mx = fmaxf(mx, __shfl_xor_sync(0xffffffffu, mx, off));
    float ex = (lane < 20) ? expf(sc - mx) : 0.f;
    float sm = ex;
#pragma unroll
    for (int off = 16; off; off >>= 1) sm += __shfl_xor_sync(0xffffffffu, sm, off);
    float beta = ex / sm;

    float a0 = 0.f, a1 = 0.f;
    for (int j = 0; j < 20; j++) {
        float bj = __shfl_sync(0xffffffffu, beta, j);
        a0 = fmaf(bj, myf[j * 42 + lane], a0);
        if (lane < 10) a1 = fmaf(bj, myf[j * 42 + 32 + lane], a1);
    }
    float* xr = x + (size_t)n * 128;
    const float* hr = h + (size_t)n * 86;
    for (int i = lane; i < 86; i += 32) xr[i] = hr[i];
    xr[86 + lane] = a0;
    if (lane < 10) xr[118 + lane] = a1;
}

// ---------------- weight prep ---------------------------------------------------------
__global__ void k_wprep(const float* __restrict__ gatW, const float* __restrict__ saw1,
                        __nv_bfloat16* __restrict__ bh, __nv_bfloat16* __restrict__ bl) {
    int idx = blockIdx.x * 256 + threadIdx.x;
    if (idx >= 4 * 16384) return;
    int slot = idx >> 14, rem = idx & 16383;
    int nIdx = rem >> 7, kIdx = rem & 127;
    float v = (slot < 3) ? gatW[slot * 16384 + kIdx * 128 + nIdx] : saw1[kIdx * 128 + nIdx];
    __nv_bfloat16 hh = __float2bfloat16(v);
    bh[idx] = hh;
    bl[idx] = __float2bfloat16(v - __bfloat162float(hh));
}

// ---------------- CSR build -----------------------------------------------------------
__global__ void k_count(const int* __restrict__ dst, int* __restrict__ deg) {
    int p = blockIdx.y;
    int e = blockIdx.x * 256 + threadIdx.x;
    if (e >= Ee) return;
    atomicAdd(&deg[(size_t)p * Nn + dst[(size_t)p * Ee + e]], 1);
}

__global__ void k_scan(const int* __restrict__ deg, int* __restrict__ off,
                       int* __restrict__ cur) {
    int p = blockIdx.x;
    int tid = threadIdx.x, lane = tid & 31, wid = tid >> 5;
    __shared__ int wsum[32];
    __shared__ int carry;
    if (tid == 0) carry = 0;
    __syncthreads();
    for (int base = 0; base < Nn; base += 1024) {
        int i = base + tid;
        int v = (i < Nn) ? deg[(size_t)p * Nn + i] : 0;
        int xv = v;
#pragma unroll
        for (int o = 1; o < 32; o <<= 1) {
            int t = __shfl_up_sync(0xffffffffu, xv, o);
            if (lane >= o) xv += t;
        }
        if (lane == 31) wsum[wid] = xv;
        __syncthreads();
        if (wid == 0) {
            int y = wsum[lane];
#pragma unroll
            for (int o = 1; o < 32; o <<= 1) {
                int t = __shfl_up_sync(0xffffffffu, y, o);
                if (lane >= o) y += t;
            }
            wsum[lane] = y;
        }
        __syncthreads();
        int wpre = (wid == 0) ? 0 : wsum[wid - 1];
        int excl = carry + wpre + xv - v;
        if (i < Nn) {
            off[(size_t)p * (Nn + 1) + i] = excl;
            cur[(size_t)p * Nn + i] = excl;
        }
        __syncthreads();
        if (tid == 1023) carry = excl + v;
        __syncthreads();
    }
    if (tid == 0) off[(size_t)p * (Nn + 1) + Nn] = carry;
}

__global__ void k_scatter(const int* __restrict__ src, const int* __restrict__ dst,
                          int* __restrict__ cur, int* __restrict__ csrc) {
    int p = blockIdx.y;
    int e = blockIdx.x * 256 + threadIdx.x;
    if (e >= Ee) return;
    int d = dst[(size_t)p * Ee + e];
    int pos = atomicAdd(&cur[(size_t)p * Nn + d], 1);
    csrc[(size_t)p * Ee + pos] = src[(size_t)p * Ee + e];
}

// ---------------- gather aggregation: warp per (p, dst) -------------------------------
__global__ void k_gather(const int* __restrict__ csrc, const int* __restrict__ off,
                         const float* __restrict__ el, const float* __restrict__ er,
                         const float* __restrict__ feat, float* __restrict__ z) {
    int p = blockIdx.y;
    int tid = threadIdx.x, wid = tid >> 5, lane = tid & 31;
    int n = blockIdx.x * 8 + wid;
    if (n >= Nn) return;
    long r = (long)p * Nn + n;
    int start = off[(size_t)p * (Nn + 1) + n];
    int end = off[(size_t)p * (Nn + 1) + n + 1];
    float* zp = &z[r * 128 + lane * 4];
    if (start == end) {
        *(float4*)zp = make_float4(0.f, 0.f, 0.f, 0.f);
        return;
    }
    const int* sp = csrc + (size_t)p * Ee;
    const float4* elp = (const float4*)el + (size_t)p * Nn;
    float4 er4 = ((const float4*)er)[r];

    float4 mx = make_float4(-INFINITY, -INFINITY, -INFINITY, -INFINITY);
    for (int i = start + lane; i < end; i += 32) {
        float4 a = elp[sp[i]];
        float vx = a.x + er4.x; vx = vx > 0.f ? vx : 0.2f * vx;
        float vy = a.y + er4.y; vy = vy > 0.f ? vy : 0.2f * vy;
        float vz = a.z + er4.z; vz = vz > 0.f ? vz : 0.2f * vz;
        float vw = a.w + er4.w; vw = vw > 0.f ? vw : 0.2f * vw;
        mx.x = fmaxf(mx.x, vx); mx.y = fmaxf(mx.y, vy);
        mx.z = fmaxf(mx.z, vz); mx.w = fmaxf(mx.w, vw);
    }
#pragma unroll
    for (int o = 16; o; o >>= 1) {
        mx.x = fmaxf(mx.x, __shfl_xor_sync(0xffffffffu, mx.x, o));
        mx.y = fmaxf(mx.y, __shfl_xor_sync(0xffffffffu, mx.y, o));
        mx.z = fmaxf(mx.z, __shfl_xor_sync(0xffffffffu, mx.z, o));
        mx.w = fmaxf(mx.w, __shfl_xor_sync(0xffffffffu, mx.w, o));
    }

    int head = lane >> 3;
    float4 acc = make_float4(0.f, 0.f, 0.f, 0.f);
    float4 zs = make_float4(0.f, 0.f, 0.f, 0.f);
    int i = start;
    for (; i + 1 < end; i += 2) {
        int s0 = sp[i], s1 = sp[i + 1];
        float4 a0 = elp[s0], a1 = elp[s1];
        float4 f0 = *(const float4*)&feat[((size_t)p * Nn + s0) * 128 + lane * 4];
        float4 f1 = *(const float4*)&feat[((size_t)p * Nn + s1) * 128 + lane * 4];
        float4 w0, w1;
        float t;
        t = a0.x + er4.x; t = t > 0.f ? t : 0.2f * t; w0.x = __expf(t - mx.x);
        t = a0.y + er4.y; t = t > 0.f ? t : 0.2f * t; w0.y = __expf(t - mx.y);
        t = a0.z + er4.z; t = t > 0.f ? t : 0.2f * t; w0.z = __expf(t - mx.z);
        t = a0.w + er4.w; t = t > 0.f ? t : 0.2f * t; w0.w = __expf(t - mx.w);
        t = a1.x + er4.x; t = t > 0.f ? t : 0.2f * t; w1.x = __expf(t - mx.x);
        t = a1.y + er4.y; t = t > 0.f ? t : 0.2f * t; w1.y = __expf(t - mx.y);
        t = a1.z + er4.z; t = t > 0.f ? t : 0.2f * t; w1.z = __expf(t - mx.z);
        t = a1.w + er4.w; t = t > 0.f ? t : 0.2f * t; w1.w = __expf(t - mx.w);
        zs.x += w0.x + w1.x; zs.y += w0.y + w1.y;
        zs.z += w0.z + w1.z; zs.w += w0.w + w1.w;
        float c0 = head == 0 ? w0.x : head == 1 ? w0.y : head == 2 ? w0.z : w0.w;
        float c1 = head == 0 ? w1.x : head == 1 ? w1.y : head == 2 ? w1.z : w1.w;
        acc.x = fmaf(c0, f0.x, acc.x); acc.x = fmaf(c1, f1.x, acc.x);
        acc.y = fmaf(c0, f0.y, acc.y); acc.y = fmaf(c1, f1.y, acc.y);
        acc.z = fmaf(c0, f0.z, acc.z); acc.z = fmaf(c1, f1.z, acc.z);
        acc.w = fmaf(c0, f0.w, acc.w); acc.w = fmaf(c1, f1.w, acc.w);
    }
    if (i < end) {
        int s0 = sp[i];
        float4 a0 = elp[s0];
        float4 f0 = *(const float4*)&feat[((size_t)p * Nn + s0) * 128 + lane * 4];
        float4 w0;
        float t;
        t = a0.x + er4.x; t = t > 0.f ? t : 0.2f * t; w0.x = __expf(t - mx.x);
        t = a0.y + er4.y; t = t > 0.f ? t : 0.2f * t; w0.y = __expf(t - mx.y);
        t = a0.z + er4.z; t = t > 0.f ? t : 0.2f * t; w0.z = __expf(t - mx.z);
        t = a0.w + er4.w; t = t > 0.f ? t : 0.2f * t; w0.w = __expf(t - mx.w);
        zs.x += w0.x; zs.y += w0.y; zs.z += w0.z; zs.w += w0.w;
        float c0 = head == 0 ? w0.x : head == 1 ? w0.y : head == 2 ? w0.z : w0.w;
        acc.x = fmaf(c0, f0.x, acc.x);
        acc.y = fmaf(c0, f0.y, acc.y);
        acc.z = fmaf(c0, f0.z, acc.z);
        acc.w = fmaf(c0, f0.w, acc.w);
    }
    float zsel = head == 0 ? zs.x : head == 1 ? zs.y : head == 2 ? zs.z : zs.w;
    float inv = 1.f / zsel;
    acc.x *= inv; acc.y *= inv; acc.z *= inv; acc.w *= inv;
    acc.x = acc.x > 0.f ? acc.x : expm1f(acc.x);
    acc.y = acc.y > 0.f ? acc.y : expm1f(acc.y);
    acc.z = acc.z > 0.f ? acc.z : expm1f(acc.z);
    acc.w = acc.w > 0.f ? acc.w : expm1f(acc.w);
    *(float4*)zp = acc;
}

// ---------------- softmax over meta-paths + combine -----------------------------------
__global__ void k_bsem(const float* __restrict__ wsem, float* __restrict__ bsem) {
    float w0 = wsem[0] / (float)Nn, w1 = wsem[1] / (float)Nn, w2 = wsem[2] / (float)Nn;
    float m = fmaxf(w0, fmaxf(w1, w2));
    float e0 = expf(w0 - m), e1 = expf(w1 - m), e2 = expf(w2 - m);
    float s = e0 + e1 + e2;
    bsem[0] = e0 / s; bsem[1] = e1 / s; bsem[2] = e2 / s;
}

__global__ void k_comb(const float* __restrict__ z, const float* __restrict__ bsem,
                       float* __restrict__ out) {
    long i = (long)blockIdx.x * 256 + threadIdx.x;
    if (i >= (long)Nn * 32) return;
    float b0 = bsem[0], b1 = bsem[1], b2 = bsem[2];
    const float4* z4 = (const float4*)z;
    float4 v0 = z4[i];
    float4 v1 = z4[(size_t)Nn * 32 + i];
    float4 v2 = z4[2 * (size_t)Nn * 32 + i];
    float4 o;
    o.x = b0 * v0.x + b1 * v1.x + b2 * v2.x;
    o.y = b0 * v0.y + b1 * v1.y + b2 * v2.y;
    o.z = b0 * v0.z + b1 * v1.z + b2 * v2.z;
    o.w = b0 * v0.w + b1 * v1.w + b2 * v2.w;
    ((float4*)out)[i] = o;
}

// ---------------- launch ----------------------------------------------------------------
extern "C" void kernel_launch(void* const* d_in, const int* in_sizes, int n_in,
                              void* d_out, int out_size) {
    const float* h      = (const float*)d_in[0];
    const float* cf     = (const float*)d_in[1];
    const float* fa_w1  = (const float*)d_in[2];
    const float* fa_b1  = (const float*)d_in[3];
    const float* fa_w2  = (const float*)d_in[4];
    const float* gat_W  = (const float*)d_in[5];
    const float* attn_l = (const float*)d_in[6];
    const float* attn_r = (const float*)d_in[7];
    const float* sa_w1  = (const float*)d_in[8];
    const float* sa_b1  = (const float*)d_in[9];
    const float* sa_w2  = (const float*)d_in[10];
    const int*   src    = (const int*)d_in[11];
    const int*   dst    = (const int*)d_in[12];
    float* out = (float*)d_out;

    float *px, *pfeat, *pz, *pel, *per, *pwsem, *pbsem;
    int *pdeg, *poff, *pcur, *pcsrc;
    __nv_bfloat16 *pbh, *pbl;
    cudaGetSymbolAddress((void**)&px, g_x);
    cudaGetSymbolAddress((void**)&pfeat, g_feat);
    cudaGetSymbolAddress((void**)&pz, g_z);
    cudaGetSymbolAddress((void**)&pel, g_el);
    cudaGetSymbolAddress((void**)&per, g_er);
    cudaGetSymbolAddress((void**)&pdeg, g_deg);
    cudaGetSymbolAddress((void**)&poff, g_off);
    cudaGetSymbolAddress((void**)&pcur, g_cur);
    cudaGetSymbolAddress((void**)&pcsrc, g_csrc);
    cudaGetSymbolAddress((void**)&pbh, g_bt_hi);
    cudaGetSymbolAddress((void**)&pbl, g_bt_lo);
    cudaGetSymbolAddress((void**)&pwsem, g_wsem);
    cudaGetSymbolAddress((void**)&pbsem, g_bsem);

    cudaFuncSetAttribute(k_gemm_feat, cudaFuncAttributeMaxDynamicSharedMemorySize, SMEM_TOT);
    cudaFuncSetAttribute(k_semgemm, cudaFuncAttributeMaxDynamicSharedMemorySize, SMEM_TOT);

    cudaMemsetAsync(pdeg, 0, sizeof(int) * (size_t)Pp * Nn, 0);
    cudaMemsetAsync(pwsem, 0, sizeof(float) * Pp, 0);

    k_wprep<<<(4 * 16384 + 255) / 256, 256>>>(gat_W, sa_w1, pbh, pbl);
    k_featatt<<<(Nn + 7) / 8, 256>>>(h, cf, fa_w1, fa_b1, fa_w2, px);

    dim3 ge((Ee + 255) / 256, Pp);
    k_count<<<ge, 256>>>(dst, pdeg);

    dim3 gg((Nn + 127) / 128, Pp);
    k_gemm_feat<<<gg, 256, SMEM_TOT>>>(px, pbh, pbl, attn_l, attn_r, pfeat, pel, per);

    k_scan<<<Pp, 1024>>>(pdeg, poff, pcur);
    k_scatter<<<ge, 256>>>(src, dst, pcur, pcsrc);

    dim3 gn((Nn + 7) / 8, Pp);
    k_gather<<<gn, 256>>>(pcsrc, poff, pel, per, pfeat, pz);

    k_semgemm<<<gg, 256, SMEM_TOT>>>(pz, pbh + 3 * 16384, pbl + 3 * 16384, sa_b1, sa_w2, pwsem);
    k_bsem<<<1, 1>>>(pwsem, pbsem);
    k_comb<<<(unsigned)(((long)Nn * 32 + 255) / 256), 256>>>(pz, pbsem, out);
}

// round 7
// speedup vs baseline: 1.2111x; 1.0414x over previous
#include <cuda_runtime.h>
#include <cuda_bf16.h>
#include <math.h>
#include <stdint.h>

#define Nn 50000
#define Ee 400000
#define Pp 3

// ---------------- scratch (device globals) --------------------------------------
__device__ __align__(16) __nv_bfloat16 g_x_hi[(size_t)Nn * 128];
__device__ __align__(16) __nv_bfloat16 g_x_lo[(size_t)Nn * 128];
__device__ __align__(16) float g_feat[(size_t)Pp * Nn * 128];
__device__ __align__(16) __nv_bfloat16 g_z_hi[(size_t)Pp * Nn * 128];
__device__ __align__(16) __nv_bfloat16 g_z_lo[(size_t)Pp * Nn * 128];
__device__ __align__(16) float g_el[(size_t)Pp * Nn * 4];
__device__ __align__(16) float g_er[(size_t)Pp * Nn * 4];
__device__ int g_deg[(size_t)Pp * Nn];
__device__ int g_off[(size_t)Pp * (Nn + 1)];
__device__ int g_cur[(size_t)Pp * Nn];
__device__ int g_csrc[(size_t)Pp * Ee];
__device__ __align__(16) __nv_bfloat16 g_bt_hi[4 * 128 * 128];  // [slot][n][k]
__device__ __align__(16) __nv_bfloat16 g_bt_lo[4 * 128 * 128];
__device__ float g_wsem[Pp];
__device__ float g_bsem[Pp];

// ---------------- smem layout ------------------------------------------------------
#define SROW 72
#define TILEB (128 * SROW * 2)        // 18432
#define S_AUX0 0
#define S_AUX1 512
#define S_RED  1024
#define S_A0H  2048
#define S_A0L  (S_A0H + TILEB)
#define S_A1H  (S_A0L + TILEB)
#define S_A1L  (S_A1H + TILEB)
#define S_BH   (S_A1L + TILEB)
#define S_BL   (S_BH + TILEB)
#define SMEM_TOT (S_BL + TILEB)       // 112640
#define SDW 132

__device__ __forceinline__ void mma16816(float& d0, float& d1, float& d2, float& d3,
                                         uint32_t a0, uint32_t a1, uint32_t a2, uint32_t a3,
                                         uint32_t b0, uint32_t b1) {
    asm volatile(
        "mma.sync.aligned.m16n8k16.row.col.f32.bf16.bf16.f32 "
        "{%0,%1,%2,%3}, {%4,%5,%6,%7}, {%8,%9}, {%0,%1,%2,%3};"
        : "+f"(d0), "+f"(d1), "+f"(d2), "+f"(d3)
        : "r"(a0), "r"(a1), "r"(a2), "r"(a3), "r"(b0), "r"(b1));
}

__device__ __forceinline__ void ldsm4(uint32_t& r0, uint32_t& r1, uint32_t& r2,
                                      uint32_t& r3, uint32_t addr) {
    asm volatile("ldmatrix.sync.aligned.m8n8.x4.shared.b16 {%0,%1,%2,%3}, [%4];"
                 : "=r"(r0), "=r"(r1), "=r"(r2), "=r"(r3) : "r"(addr));
}

__device__ __forceinline__ void cpa16(uint32_t dst, const void* src, int sz) {
    asm volatile("cp.async.cg.shared.global [%0], [%1], 16, %2;"
                 :: "r"(dst), "l"(src), "r"(sz));
}
#define CP_COMMIT() asm volatile("cp.async.commit_group;" ::: "memory")
#define CP_WAIT(n)  asm volatile("cp.async.wait_group %0;" :: "n"(n) : "memory")

// fill one A slab buffer (hi+lo) via cp.async
__device__ __forceinline__ void fill_A(uint32_t sbase, const __nv_bfloat16* ah,
                                       const __nv_bfloat16* al, int n0, int slab, int tid) {
#pragma unroll
    for (int it = 0; it < 8; it++) {
        int idx = it * 256 + tid;          // 0..2047
        int prec = idx >> 10;
        int rem = idx & 1023;
        int row = rem >> 3;
        int ch = rem & 7;
        int n = n0 + row;
        int nc = n < Nn ? n : Nn - 1;
        const __nv_bfloat16* s = (prec ? al : ah) + (size_t)nc * 128 + slab * 64 + ch * 8;
        uint32_t d = sbase + (uint32_t)(prec * TILEB + (row * SROW + ch * 8) * 2);
        cpa16(d, s, n < Nn ? 16 : 0);
    }
}

__device__ __forceinline__ void fill_B(uint32_t sbase, const __nv_bfloat16* bh,
                                       const __nv_bfloat16* bl, int slab, int tid) {
#pragma unroll
    for (int it = 0; it < 8; it++) {
        int idx = it * 256 + tid;
        int prec = idx >> 10;
        int rem = idx & 1023;
        int row = rem >> 3;
        int ch = rem & 7;
        const __nv_bfloat16* s = (prec ? bl : bh) + (size_t)row * 128 + slab * 64 + ch * 8;
        uint32_t d = sbase + (uint32_t)(prec * TILEB + (row * SROW + ch * 8) * 2);
        cpa16(d, s, 16);
    }
}

// MMA over one slab buffer (hi/lo pair at abase, abase+TILEB)
__device__ __forceinline__ void mma_slab(uint32_t smem_s, uint32_t abase, float d[2][8][4],
                                         int lane, int wid) {
    int warpM = wid & 3, warpN = wid >> 2;
    int grp = lane >> 3, lr = lane & 7;
    uint32_t aA = smem_s + abase +
        (uint32_t)(((warpM * 32 + lr + (grp & 1) * 8) * SROW + (grp >> 1) * 8) * 2);
    uint32_t aB = smem_s + S_BH +
        (uint32_t)(((warpN * 64 + lr + (grp >> 1) * 8) * SROW + (grp & 1) * 8) * 2);
    const uint32_t MT = 16 * SROW * 2;

#pragma unroll
    for (int ks = 0; ks < 4; ks++) {
        uint32_t kb = (uint32_t)(ks * 32);
        uint32_t ah[2][4], al[2][4], bb[4][4];
#pragma unroll
        for (int mt = 0; mt < 2; mt++) {
            ldsm4(ah[mt][0], ah[mt][1], ah[mt][2], ah[mt][3], aA + mt * MT + kb);
            ldsm4(al[mt][0], al[mt][1], al[mt][2], al[mt][3], aA + TILEB + mt * MT + kb);
        }
#pragma unroll
        for (int np = 0; np < 4; np++)
            ldsm4(bb[np][0], bb[np][1], bb[np][2], bb[np][3], aB + np * MT + kb);
#pragma unroll
        for (int np = 0; np < 4; np++)
#pragma unroll
            for (int mt = 0; mt < 2; mt++) {
                mma16816(d[mt][2 * np][0], d[mt][2 * np][1], d[mt][2 * np][2], d[mt][2 * np][3],
                         ah[mt][0], ah[mt][1], ah[mt][2], ah[mt][3], bb[np][0], bb[np][1]);
                mma16816(d[mt][2 * np + 1][0], d[mt][2 * np + 1][1], d[mt][2 * np + 1][2], d[mt][2 * np + 1][3],
                         ah[mt][0], ah[mt][1], ah[mt][2], ah[mt][3], bb[np][2], bb[np][3]);
            }
#pragma unroll
        for (int np = 0; np < 4; np++)
#pragma unroll
            for (int mt = 0; mt < 2; mt++) {
                mma16816(d[mt][2 * np][0], d[mt][2 * np][1], d[mt][2 * np][2], d[mt][2 * np][3],
                         al[mt][0], al[mt][1], al[mt][2], al[mt][3], bb[np][0], bb[np][1]);
                mma16816(d[mt][2 * np + 1][0], d[mt][2 * np + 1][1], d[mt][2 * np + 1][2], d[mt][2 * np + 1][3],
                         al[mt][0], al[mt][1], al[mt][2], al[mt][3], bb[np][2], bb[np][3]);
            }
#pragma unroll
        for (int np = 0; np < 4; np++)
            ldsm4(bb[np][0], bb[np][1], bb[np][2], bb[np][3], aB + TILEB + np * MT + kb);
#pragma unroll
        for (int np = 0; np < 4; np++)
#pragma unroll
            for (int mt = 0; mt < 2; mt++) {
                mma16816(d[mt][2 * np][0], d[mt][2 * np][1], d[mt][2 * np][2], d[mt][2 * np][3],
                         ah[mt][0], ah[mt][1], ah[mt][2], ah[mt][3], bb[np][0], bb[np][1]);
                mma16816(d[mt][2 * np + 1][0], d[mt][2 * np + 1][1], d[mt][2 * np + 1][2], d[mt][2 * np + 1][3],
                         ah[mt][0], ah[mt][1], ah[mt][2], ah[mt][3], bb[np][2], bb[np][3]);
            }
    }
}

// pipelined core: A double-buffered, B refilled between slabs
__device__ __forceinline__ void gemm_core(const __nv_bfloat16* __restrict__ ah,
                                          const __nv_bfloat16* __restrict__ alo,
                                          int n0,
                                          const __nv_bfloat16* __restrict__ bth,
                                          const __nv_bfloat16* __restrict__ btl,
                                          char* smem, float d[2][8][4]) {
    int tid = threadIdx.x, lane = tid & 31, wid = tid >> 5;
    uint32_t smem_s = (uint32_t)__cvta_generic_to_shared(smem);

    fill_B(smem_s + S_BH, bth, btl, 0, tid);
    fill_A(smem_s + S_A0H, ah, alo, n0, 0, tid);
    CP_COMMIT();                       // g0: slab0
    fill_A(smem_s + S_A1H, ah, alo, n0, 1, tid);
    CP_COMMIT();                       // g1: A slab1
    CP_WAIT(1);
    __syncthreads();
    mma_slab(smem_s, S_A0H, d, lane, wid);
    __syncthreads();
    fill_B(smem_s + S_BH, bth, btl, 1, tid);
    CP_COMMIT();                       // g2: B slab1
    CP_WAIT(0);
    __syncthreads();
    mma_slab(smem_s, S_A1H, d, lane, wid);
    __syncthreads();
}

__device__ __forceinline__ void stage_d(float* sd, float d[2][8][4], int lane, int wid) {
    int warpM = wid & 3, warpN = wid >> 2;
    int rq = lane >> 2, cq = (lane & 3) * 2;
#pragma unroll
    for (int mt = 0; mt < 2; mt++) {
        int rl0 = warpM * 32 + mt * 16 + rq;
        int rl1 = rl0 + 8;
#pragma unroll
        for (int nt = 0; nt < 8; nt++) {
            int c = warpN * 64 + nt * 8 + cq;
            *(float2*)&sd[rl0 * SDW + c] = make_float2(d[mt][nt][0], d[mt][nt][1]);
            *(float2*)&sd[rl1 * SDW + c] = make_float2(d[mt][nt][2], d[mt][nt][3]);
        }
    }
}

// ---------------- projection GEMM + fused el/er -----------------------------------
__global__ void __launch_bounds__(256, 2) k_gemm_feat(
    const __nv_bfloat16* __restrict__ xh, const __nv_bfloat16* __restrict__ xl,
    const __nv_bfloat16* __restrict__ bth, const __nv_bfloat16* __restrict__ btl,
    const float* __restrict__ al, const float* __restrict__ ar,
    float* __restrict__ feat, float* __restrict__ el, float* __restrict__ er) {
    extern __shared__ char smem[];
    int tid = threadIdx.x, lane = tid & 31, wid = tid >> 5;
    int p = blockIdx.y;
    int n0 = blockIdx.x * 128;
    float* sal = (float*)(smem + S_AUX0);
    float* sar = (float*)(smem + S_AUX1);
    if (tid < 128) { sal[tid] = al[p * 128 + tid]; sar[tid] = ar[p * 128 + tid]; }

    float d[2][8][4];
#pragma unroll
    for (int mt = 0; mt < 2; mt++)
#pragma unroll
        for (int nt = 0; nt < 8; nt++)
#pragma unroll
            for (int q = 0; q < 4; q++) d[mt][nt][q] = 0.f;

    gemm_core(xh, xl, n0, bth + (size_t)p * 16384, btl + (size_t)p * 16384, smem, d);

    float* sd = (float*)(smem + S_A0H);
    stage_d(sd, d, lane, wid);
    __syncthreads();

    int row = tid >> 1, half = tid & 1;
    int n = n0 + row;
    if (n < Nn) {
        float sel[2] = {0.f, 0.f}, ser[2] = {0.f, 0.f};
        float4* o = (float4*)&feat[((size_t)p * Nn + n) * 128 + half * 64];
#pragma unroll
        for (int q = 0; q < 16; q++) {
            float4 v = *(float4*)&sd[row * SDW + half * 64 + q * 4];
            o[q] = v;
            int hb = q >> 3;
            int c = half * 64 + q * 4;
            sel[hb] = fmaf(v.x, sal[c + 0], sel[hb]);
            sel[hb] = fmaf(v.y, sal[c + 1], sel[hb]);
            sel[hb] = fmaf(v.z, sal[c + 2], sel[hb]);
            sel[hb] = fmaf(v.w, sal[c + 3], sel[hb]);
            ser[hb] = fmaf(v.x, sar[c + 0], ser[hb]);
            ser[hb] = fmaf(v.y, sar[c + 1], ser[hb]);
            ser[hb] = fmaf(v.z, sar[c + 2], ser[hb]);
            ser[hb] = fmaf(v.w, sar[c + 3], ser[hb]);
        }
        *(float2*)&el[((size_t)p * Nn + n) * 4 + half * 2] = make_float2(sel[0], sel[1]);
        *(float2*)&er[((size_t)p * Nn + n) * 4 + half * 2] = make_float2(ser[0], ser[1]);
    }
}

// ---------------- semantic GEMM + tanh/w2 reduce ------------------------------------
__global__ void __launch_bounds__(256, 2) k_semgemm(
    const __nv_bfloat16* __restrict__ zh, const __nv_bfloat16* __restrict__ zl,
    const __nv_bfloat16* __restrict__ bth, const __nv_bfloat16* __restrict__ btl,
    const float* __restrict__ b1, const float* __restrict__ w2, float* __restrict__ wsem) {
    extern __shared__ char smem[];
    int tid = threadIdx.x, lane = tid & 31, wid = tid >> 5;
    int p = blockIdx.y;
    int n0 = blockIdx.x * 128;
    float* sb1 = (float*)(smem + S_AUX0);
    float* sw2 = (float*)(smem + S_AUX1);
    float* sred = (float*)(smem + S_RED);
    if (tid < 128) { sb1[tid] = b1[tid]; sw2[tid] = w2[tid]; }

    float d[2][8][4];
#pragma unroll
    for (int mt = 0; mt < 2; mt++)
#pragma unroll
        for (int nt = 0; nt < 8; nt++)
#pragma unroll
            for (int q = 0; q < 4; q++) d[mt][nt][q] = 0.f;

    gemm_core(zh + (size_t)p * Nn * 128, zl + (size_t)p * Nn * 128, n0, bth, btl, smem, d);

    float* sd = (float*)(smem + S_A0H);
    stage_d(sd, d, lane, wid);
    __syncthreads();

    int row = tid >> 1, half = tid & 1;
    int n = n0 + row;
    float accv = 0.f;
    if (n < Nn) {
#pragma unroll
        for (int q = 0; q < 16; q++) {
            float4 v = *(float4*)&sd[row * SDW + half * 64 + q * 4];
            int c = half * 64 + q * 4;
            accv = fmaf(tanhf(v.x + sb1[c + 0]), sw2[c + 0], accv);
            accv = fmaf(tanhf(v.y + sb1[c + 1]), sw2[c + 1], accv);
            accv = fmaf(tanhf(v.z + sb1[c + 2]), sw2[c + 2], accv);
            accv = fmaf(tanhf(v.w + sb1[c + 3]), sw2[c + 3], accv);
        }
    }
#pragma unroll
    for (int o = 16; o; o >>= 1) accv += __shfl_xor_sync(0xffffffffu, accv, o);
    if (lane == 0) sred[wid] = accv;
    __syncthreads();
    if (tid == 0) {
        float s = 0.f;
#pragma unroll
        for (int i = 0; i < 8; i++) s += sred[i];
        atomicAdd(&wsem[p], s);
    }
}

// ---------------- feature attention: warp per node ----------------------------------
__global__ void k_featatt(const float* __restrict__ h, const float* __restrict__ cf,
                          const float* __restrict__ w1, const float* __restrict__ b1,
                          const float* __restrict__ w2,
                          __nv_bfloat16* __restrict__ xh, __nv_bfloat16* __restrict__ xl) {
    __shared__ float sw1[42 * 16];
    __shared__ float sb1[16], sw2[16];
    __shared__ float sf[8][840];
    __shared__ float ss[8][20];
    int tid = threadIdx.x, wid = tid >> 5, lane = tid & 31;
    for (int i = tid; i < 672; i += 256) sw1[i] = w1[i];
    if (tid < 16) { sb1[tid] = b1[tid]; sw2[tid] = w2[tid]; }
    __syncthreads();
    int n = blockIdx.x * 8 + wid;
    if (n >= Nn) return;

    const float* fr = cf + (size_t)n * 840;
    float* myf = sf[wid];
    for (int i = lane; i < 840; i += 32) myf[i] = fr[i];
    __syncwarp();

    int k = lane & 15;
    for (int j0 = 0; j0 < 20; j0 += 2) {
        int j = j0 + (lane >> 4);
        const float* fj = myf + j * 42;
        float acc = sb1[k];
#pragma unroll
        for (int i = 0; i < 42; i++) acc = fmaf(fj[i], sw1[i * 16 + k], acc);
        float v = tanhf(acc) * sw2[k];
#pragma unroll
        for (int off = 8; off; off >>= 1) v += __shfl_down_sync(0xffffffffu, v, off);
        if (k == 0) ss[wid][j] = v;
    }
    __syncwarp();

    float sc = (lane < 20) ? ss[wid][lane] : -INFINITY;
    float mx = sc;
#pragma unroll
    for (int off = 16; off; off >>= 1) mx = fmaxf(mx, __shfl_xor_sync(0xffffffffu, mx, off));
    float ex = (lane < 20) ? expf(sc - mx) : 0.f;
    float sm = ex;
#pragma unroll
    for (int off = 16; off; off >>= 1) sm += __shfl_xor_sync(0xffffffffu, sm, off);
    float beta = ex / sm;

    float a0 = 0.f, a1 = 0.f;
    for (int j = 0; j < 20; j++) {
        float bj = __shfl_sync(0xffffffffu, beta, j);
        a0 = fmaf(bj, myf[j * 42 + lane], a0);
        if (lane < 10) a1 = fmaf(bj, myf[j * 42 + 32 + lane], a1);
    }
    const float* hr = h + (size_t)n * 86;
    __nv_bfloat16* xhr = xh + (size_t)n * 128;
    __nv_bfloat16* xlr = xl + (size_t)n * 128;
    for (int i = lane; i < 86; i += 32) {
        float v = hr[i];
        __nv_bfloat16 hh = __float2bfloat16(v);
        xhr[i] = hh;
        xlr[i] = __float2bfloat16(v - __bfloat162float(hh));
    }
    {
        __nv_bfloat16 hh = __float2bfloat16(a0);
        xhr[86 + lane] = hh;
        xlr[86 + lane] = __float2bfloat16(a0 - __bfloat162float(hh));
    }
    if (lane < 10) {
        __nv_bfloat16 hh = __float2bfloat16(a1);
        xhr[118 + lane] = hh;
        xlr[118 + lane] = __float2bfloat16(a1 - __bfloat162float(hh));
    }
}

// ---------------- weight prep ---------------------------------------------------------
__global__ void k_wprep(const float* __restrict__ gatW, const float* __restrict__ saw1,
                        __nv_bfloat16* __restrict__ bh, __nv_bfloat16* __restrict__ bl) {
    int idx = blockIdx.x * 256 + threadIdx.x;
    if (idx >= 4 * 16384) return;
    int slot = idx >> 14, rem = idx & 16383;
    int nIdx = rem >> 7, kIdx = rem & 127;
    float v = (slot < 3) ? gatW[slot * 16384 + kIdx * 128 + nIdx] : saw1[kIdx * 128 + nIdx];
    __nv_bfloat16 hh = __float2bfloat16(v);
    bh[idx] = hh;
    bl[idx] = __float2bfloat16(v - __bfloat162float(hh));
}

// ---------------- CSR build (4-way ILP atomics) ----------------------------------------
__global__ void k_count(const int* __restrict__ dst, int* __restrict__ deg) {
    int p = blockIdx.y;
    int base = blockIdx.x * 1024 + threadIdx.x;
#pragma unroll
    for (int j = 0; j < 4; j++) {
        int e = base + j * 256;
        if (e < Ee) atomicAdd(&deg[(size_t)p * Nn + dst[(size_t)p * Ee + e]], 1);
    }
}

__global__ void k_scan(const int* __restrict__ deg, int* __restrict__ off,
                       int* __restrict__ cur) {
    int p = blockIdx.x;
    int tid = threadIdx.x, lane = tid & 31, wid = tid >> 5;
    __shared__ int wsum[32];
    __shared__ int carry;
    if (tid == 0) carry = 0;
    __syncthreads();
    for (int base = 0; base < Nn; base += 1024) {
        int i = base + tid;
        int v = (i < Nn) ? deg[(size_t)p * Nn + i] : 0;
        int xv = v;
#pragma unroll
        for (int o = 1; o < 32; o <<= 1) {
            int t = __shfl_up_sync(0xffffffffu, xv, o);
            if (lane >= o) xv += t;
        }
        if (lane == 31) wsum[wid] = xv;
        __syncthreads();
        if (wid == 0) {
            int y = wsum[lane];
#pragma unroll
            for (int o = 1; o < 32; o <<= 1) {
                int t = __shfl_up_sync(0xffffffffu, y, o);
                if (lane >= o) y += t;
            }
            wsum[lane] = y;
        }
        __syncthreads();
        int wpre = (wid == 0) ? 0 : wsum[wid - 1];
        int excl = carry + wpre + xv - v;
        if (i < Nn) {
            off[(size_t)p * (Nn + 1) + i] = excl;
            cur[(size_t)p * Nn + i] = excl;
        }
        __syncthreads();
        if (tid == 1023) carry = excl + v;
        __syncthreads();
    }
    if (tid == 0) off[(size_t)p * (Nn + 1) + Nn] = carry;
}

__global__ void k_scatter(const int* __restrict__ src, const int* __restrict__ dst,
                          int* __restrict__ cur, int* __restrict__ csrc) {
    int p = blockIdx.y;
    int base = blockIdx.x * 1024 + threadIdx.x;
    int ev[4], dv[4], sv[4];
#pragma unroll
    for (int j = 0; j < 4; j++) {
        ev[j] = base + j * 256;
        if (ev[j] < Ee) {
            dv[j] = dst[(size_t)p * Ee + ev[j]];
            sv[j] = src[(size_t)p * Ee + ev[j]];
        }
    }
#pragma unroll
    for (int j = 0; j < 4; j++) {
        if (ev[j] < Ee) {
            int pos = atomicAdd(&cur[(size_t)p * Nn + dv[j]], 1);
            csrc[(size_t)p * Ee + pos] = sv[j];
        }
    }
}

// ---------------- gather aggregation: warp per (p, dst) -------------------------------
__global__ void k_gather(const int* __restrict__ csrc, const int* __restrict__ off,
                         const float* __restrict__ el, const float* __restrict__ er,
                         const float* __restrict__ feat,
                         __nv_bfloat16* __restrict__ zh, __nv_bfloat16* __restrict__ zl) {
    int p = blockIdx.y;
    int tid = threadIdx.x, wid = tid >> 5, lane = tid & 31;
    int n = blockIdx.x * 8 + wid;
    if (n >= Nn) return;
    long r = (long)p * Nn + n;
    int start = off[(size_t)p * (Nn + 1) + n];
    int end = off[(size_t)p * (Nn + 1) + n + 1];
    float4 acc = make_float4(0.f, 0.f, 0.f, 0.f);
    if (start < end) {
        const int* sp = csrc + (size_t)p * Ee;
        const float4* elp = (const float4*)el + (size_t)p * Nn;
        float4 er4 = ((const float4*)er)[r];

        float4 mx = make_float4(-INFINITY, -INFINITY, -INFINITY, -INFINITY);
        for (int i = start + lane; i < end; i += 32) {
            float4 a = elp[sp[i]];
            float vx = a.x + er4.x; vx = vx > 0.f ? vx : 0.2f * vx;
            float vy = a.y + er4.y; vy = vy > 0.f ? vy : 0.2f * vy;
            float vz = a.z + er4.z; vz = vz > 0.f ? vz : 0.2f * vz;
            float vw = a.w + er4.w; vw = vw > 0.f ? vw : 0.2f * vw;
            mx.x = fmaxf(mx.x, vx); mx.y = fmaxf(mx.y, vy);
            mx.z = fmaxf(mx.z, vz); mx.w = fmaxf(mx.w, vw);
        }
#pragma unroll
        for (int o = 16; o; o >>= 1) {
            mx.x = fmaxf(mx.x, __shfl_xor_sync(0xffffffffu, mx.x, o));
            mx.y = fmaxf(mx.y, __shfl_xor_sync(0xffffffffu, mx.y, o));
            mx.z = fmaxf(mx.z, __shfl_xor_sync(0xffffffffu, mx.z, o));
            mx.w = fmaxf(mx.w, __shfl_xor_sync(0xffffffffu, mx.w, o));
        }

        int head = lane >> 3;
        float4 zs = make_float4(0.f, 0.f, 0.f, 0.f);
        int i = start;
        for (; i + 1 < end; i += 2) {
            int s0 = sp[i], s1 = sp[i + 1];
            float4 a0 = elp[s0], a1 = elp[s1];
            float4 f0 = *(const float4*)&feat[((size_t)p * Nn + s0) * 128 + lane * 4];
            float4 f1 = *(const float4*)&feat[((size_t)p * Nn + s1) * 128 + lane * 4];
            float4 w0, w1;
            float t;
            t = a0.x + er4.x; t = t > 0.f ? t : 0.2f * t; w0.x = __expf(t - mx.x);
            t = a0.y + er4.y; t = t > 0.f ? t : 0.2f * t; w0.y = __expf(t - mx.y);
            t = a0.z + er4.z; t = t > 0.f ? t : 0.2f * t; w0.z = __expf(t - mx.z);
            t = a0.w + er4.w; t = t > 0.f ? t : 0.2f * t; w0.w = __expf(t - mx.w);
            t = a1.x + er4.x; t = t > 0.f ? t : 0.2f * t; w1.x = __expf(t - mx.x);
            t = a1.y + er4.y; t = t > 0.f ? t : 0.2f * t; w1.y = __expf(t - mx.y);
            t = a1.z + er4.z; t = t > 0.f ? t : 0.2f * t; w1.z = __expf(t - mx.z);
            t = a1.w + er4.w; t = t > 0.f ? t : 0.2f * t; w1.w = __expf(t - mx.w);
            zs.x += w0.x + w1.x; zs.y += w0.y + w1.y;
            zs.z += w0.z + w1.z; zs.w += w0.w + w1.w;
            float c0 = head == 0 ? w0.x : head == 1 ? w0.y : head == 2 ? w0.z : w0.w;
            float c1 = head == 0 ? w1.x : head == 1 ? w1.y : head == 2 ? w1.z : w1.w;
            acc.x = fmaf(c0, f0.x, acc.x); acc.x = fmaf(c1, f1.x, acc.x);
            acc.y = fmaf(c0, f0.y, acc.y); acc.y = fmaf(c1, f1.y, acc.y);
            acc.z = fmaf(c0, f0.z, acc.z); acc.z = fmaf(c1, f1.z, acc.z);
            acc.w = fmaf(c0, f0.w, acc.w); acc.w = fmaf(c1, f1.w, acc.w);
        }
        if (i < end) {
            int s0 = sp[i];
            float4 a0 = elp[s0];
            float4 f0 = *(const float4*)&feat[((size_t)p * Nn + s0) * 128 + lane * 4];
            float4 w0;
            float t;
            t = a0.x + er4.x; t = t > 0.f ? t : 0.2f * t; w0.x = __expf(t - mx.x);
            t = a0.y + er4.y; t = t > 0.f ? t : 0.2f * t; w0.y = __expf(t - mx.y);
            t = a0.z + er4.z; t = t > 0.f ? t : 0.2f * t; w0.z = __expf(t - mx.z);
            t = a0.w + er4.w; t = t > 0.f ? t : 0.2f * t; w0.w = __expf(t - mx.w);
            zs.x += w0.x; zs.y += w0.y; zs.z += w0.z; zs.w += w0.w;
            float c0 = head == 0 ? w0.x : head == 1 ? w0.y : head == 2 ? w0.z : w0.w;
            acc.x = fmaf(c0, f0.x, acc.x);
            acc.y = fmaf(c0, f0.y, acc.y);
            acc.z = fmaf(c0, f0.z, acc.z);
            acc.w = fmaf(c0, f0.w, acc.w);
        }
        float zsel = head == 0 ? zs.x : head == 1 ? zs.y : head == 2 ? zs.z : zs.w;
        float inv = 1.f / zsel;
        acc.x *= inv; acc.y *= inv; acc.z *= inv; acc.w *= inv;
        acc.x = acc.x > 0.f ? acc.x : expm1f(acc.x);
        acc.y = acc.y > 0.f ? acc.y : expm1f(acc.y);
        acc.z = acc.z > 0.f ? acc.z : expm1f(acc.z);
        acc.w = acc.w > 0.f ? acc.w : expm1f(acc.w);
    }
    // split to bf16 hi/lo and store packed
    __nv_bfloat16 hv[4], lv[4];
#pragma unroll
    for (int q = 0; q < 4; q++) {
        float v = (&acc.x)[q];
        __nv_bfloat16 hh = __float2bfloat16(v);
        hv[q] = hh;
        lv[q] = __float2bfloat16(v - __bfloat162float(hh));
    }
    *(uint2*)&zh[(size_t)r * 128 + lane * 4] = *(uint2*)hv;
    *(uint2*)&zl[(size_t)r * 128 + lane * 4] = *(uint2*)lv;
}

// ---------------- softmax over meta-paths + combine -----------------------------------
__global__ void k_bsem(const float* __restrict__ wsem, float* __restrict__ bsem) {
    float w0 = wsem[0] / (float)Nn, w1 = wsem[1] / (float)Nn, w2 = wsem[2] / (float)Nn;
    float m = fmaxf(w0, fmaxf(w1, w2));
    float e0 = expf(w0 - m), e1 = expf(w1 - m), e2 = expf(w2 - m);
    float s = e0 + e1 + e2;
    bsem[0] = e0 / s; bsem[1] = e1 / s; bsem[2] = e2 / s;
}

__global__ void k_comb(const __nv_bfloat16* __restrict__ zh, const __nv_bfloat16* __restrict__ zl,
                       const float* __restrict__ bsem, float* __restrict__ out) {
    long i = (long)blockIdx.x * 256 + threadIdx.x;   // over Nn*32 groups of 4 cols
    if (i >= (long)Nn * 32) return;
    float b[3] = {bsem[0], bsem[1], bsem[2]};
    float4 o = make_float4(0.f, 0.f, 0.f, 0.f);
#pragma unroll
    for (int p = 0; p < 3; p++) {
        size_t base = (size_t)p * Nn * 128 + i * 4;
        uint2 uh = *(const uint2*)&zh[base];
        uint2 ul = *(const uint2*)&zl[base];
        float2 h0 = __bfloat1622float2(*(__nv_bfloat162*)&uh.x);
        float2 h1 = __bfloat1622float2(*(__nv_bfloat162*)&uh.y);
        float2 l0 = __bfloat1622float2(*(__nv_bfloat162*)&ul.x);
        float2 l1 = __bfloat1622float2(*(__nv_bfloat162*)&ul.y);
        o.x = fmaf(b[p], h0.x + l0.x, o.x);
        o.y = fmaf(b[p], h0.y + l0.y, o.y);
        o.z = fmaf(b[p], h1.x + l1.x, o.z);
        o.w = fmaf(b[p], h1.y + l1.y, o.w);
    }
    ((float4*)out)[i] = o;
}

// ---------------- launch ----------------------------------------------------------------
extern "C" void kernel_launch(void* const* d_in, const int* in_sizes, int n_in,
                              void* d_out, int out_size) {
    const float* h      = (const float*)d_in[0];
    const float* cf     = (const float*)d_in[1];
    const float* fa_w1  = (const float*)d_in[2];
    const float* fa_b1  = (const float*)d_in[3];
    const float* fa_w2  = (const float*)d_in[4];
    const float* gat_W  = (const float*)d_in[5];
    const float* attn_l = (const float*)d_in[6];
    const float* attn_r = (const float*)d_in[7];
    const float* sa_w1  = (const float*)d_in[8];
    const float* sa_b1  = (const float*)d_in[9];
    const float* sa_w2  = (const float*)d_in[10];
    const int*   src    = (const int*)d_in[11];
    const int*   dst    = (const int*)d_in[12];
    float* out = (float*)d_out;

    float *pfeat, *pel, *per, *pwsem, *pbsem;
    int *pdeg, *poff, *pcur, *pcsrc;
    __nv_bfloat16 *pbh, *pbl, *pxh, *pxl, *pzh, *pzl;
    cudaGetSymbolAddress((void**)&pxh, g_x_hi);
    cudaGetSymbolAddress((void**)&pxl, g_x_lo);
    cudaGetSymbolAddress((void**)&pfeat, g_feat);
    cudaGetSymbolAddress((void**)&pzh, g_z_hi);
    cudaGetSymbolAddress((void**)&pzl, g_z_lo);
    cudaGetSymbolAddress((void**)&pel, g_el);
    cudaGetSymbolAddress((void**)&per, g_er);
    cudaGetSymbolAddress((void**)&pdeg, g_deg);
    cudaGetSymbolAddress((void**)&poff, g_off);
    cudaGetSymbolAddress((void**)&pcur, g_cur);
    cudaGetSymbolAddress((void**)&pcsrc, g_csrc);
    cudaGetSymbolAddress((void**)&pbh, g_bt_hi);
    cudaGetSymbolAddress((void**)&pbl, g_bt_lo);
    cudaGetSymbolAddress((void**)&pwsem, g_wsem);
    cudaGetSymbolAddress((void**)&pbsem, g_bsem);

    cudaFuncSetAttribute(k_gemm_feat, cudaFuncAttributeMaxDynamicSharedMemorySize, SMEM_TOT);
    cudaFuncSetAttribute(k_semgemm, cudaFuncAttributeMaxDynamicSharedMemorySize, SMEM_TOT);

    cudaMemsetAsync(pdeg, 0, sizeof(int) * (size_t)Pp * Nn, 0);
    cudaMemsetAsync(pwsem, 0, sizeof(float) * Pp, 0);

    k_wprep<<<(4 * 16384 + 255) / 256, 256>>>(gat_W, sa_w1, pbh, pbl);
    k_featatt<<<(Nn + 7) / 8, 256>>>(h, cf, fa_w1, fa_b1, fa_w2, pxh, pxl);

    dim3 ge4((Ee + 1023) / 1024, Pp);
    k_count<<<ge4, 256>>>(dst, pdeg);

    dim3 gg((Nn + 127) / 128, Pp);
    k_gemm_feat<<<gg, 256, SMEM_TOT>>>(pxh, pxl, pbh, pbl, attn_l, attn_r, pfeat, pel, per);

    k_scan<<<Pp, 1024>>>(pdeg, poff, pcur);
    k_scatter<<<ge4, 256>>>(src, dst, pcur, pcsrc);

    dim3 gn((Nn + 7) / 8, Pp);
    k_gather<<<gn, 256>>>(pcsrc, poff, pel, per, pfeat, pzh, pzl);

    k_semgemm<<<gg, 256, SMEM_TOT>>>(pzh, pzl, pbh + 3 * 16384, pbl + 3 * 16384, sa_b1, sa_w2, pwsem);
    k_bsem<<<1, 1>>>(pwsem, pbsem);
    k_comb<<<(unsigned)(((long)Nn * 32 + 255) / 256), 256>>>(pzh, pzl, pbsem, out);
}

// round 8
// speedup vs baseline: 1.3768x; 1.1368x over previous
#include <cuda_runtime.h>
#include <cuda_bf16.h>
#include <math.h>
#include <stdint.h>

#define Nn 50000
#define Ee 400000
#define Pp 3

// ---------------- scratch (device globals) --------------------------------------
__device__ __align__(16) __nv_bfloat16 g_x_hi[(size_t)Nn * 128];
__device__ __align__(16) __nv_bfloat16 g_x_lo[(size_t)Nn * 128];
__device__ __align__(16) float g_feat[(size_t)Pp * Nn * 128];
__device__ __align__(16) __nv_bfloat16 g_z_hi[(size_t)Pp * Nn * 128];
__device__ __align__(16) __nv_bfloat16 g_z_lo[(size_t)Pp * Nn * 128];
__device__ __align__(16) float g_el[(size_t)Pp * Nn * 4];
__device__ __align__(16) float g_er[(size_t)Pp * Nn * 4];
__device__ int g_deg[(size_t)Pp * Nn];
__device__ int g_off[(size_t)Pp * (Nn + 1)];
__device__ int g_cur[(size_t)Pp * Nn];
__device__ int g_csrc[(size_t)Pp * Ee];
__device__ __align__(16) __nv_bfloat16 g_bt_hi[4 * 128 * 128];  // [slot][n][k]
__device__ __align__(16) __nv_bfloat16 g_bt_lo[4 * 128 * 128];
__device__ float g_wsem[Pp];
__device__ float g_bsem[Pp];

// ---------------- smem layout ------------------------------------------------------
#define SROW 72
#define TILEB (128 * SROW * 2)        // 18432
#define S_AUX0 0
#define S_AUX1 512
#define S_RED  1024
#define S_A0H  2048
#define S_A0L  (S_A0H + TILEB)
#define S_A1H  (S_A0L + TILEB)
#define S_A1L  (S_A1H + TILEB)
#define S_BH   (S_A1L + TILEB)
#define S_BL   (S_BH + TILEB)
#define SMEM_TOT (S_BL + TILEB)       // 112640
#define SDW 132

__device__ __forceinline__ void mma16816(float& d0, float& d1, float& d2, float& d3,
                                         uint32_t a0, uint32_t a1, uint32_t a2, uint32_t a3,
                                         uint32_t b0, uint32_t b1) {
    asm volatile(
        "mma.sync.aligned.m16n8k16.row.col.f32.bf16.bf16.f32 "
        "{%0,%1,%2,%3}, {%4,%5,%6,%7}, {%8,%9}, {%0,%1,%2,%3};"
        : "+f"(d0), "+f"(d1), "+f"(d2), "+f"(d3)
        : "r"(a0), "r"(a1), "r"(a2), "r"(a3), "r"(b0), "r"(b1));
}

__device__ __forceinline__ void ldsm4(uint32_t& r0, uint32_t& r1, uint32_t& r2,
                                      uint32_t& r3, uint32_t addr) {
    asm volatile("ldmatrix.sync.aligned.m8n8.x4.shared.b16 {%0,%1,%2,%3}, [%4];"
                 : "=r"(r0), "=r"(r1), "=r"(r2), "=r"(r3) : "r"(addr));
}

__device__ __forceinline__ void cpa16(uint32_t dst, const void* src, int sz) {
    asm volatile("cp.async.cg.shared.global [%0], [%1], 16, %2;"
                 :: "r"(dst), "l"(src), "r"(sz));
}
#define CP_COMMIT() asm volatile("cp.async.commit_group;" ::: "memory")
#define CP_WAIT(n)  asm volatile("cp.async.wait_group %0;" :: "n"(n) : "memory")

// fill one A slab buffer via cp.async; FULL=true fills hi+lo, else hi only
template <bool FULL>
__device__ __forceinline__ void fill_A(uint32_t sbase, const __nv_bfloat16* ah,
                                       const __nv_bfloat16* al, int n0, int slab, int tid) {
    const int ITS = FULL ? 8 : 4;
#pragma unroll
    for (int it = 0; it < ITS; it++) {
        int idx = it * 256 + tid;          // 0..2047 (full) / 0..1023 (hi)
        int prec = idx >> 10;
        int rem = idx & 1023;
        int row = rem >> 3;
        int ch = rem & 7;
        int n = n0 + row;
        int nc = n < Nn ? n : Nn - 1;
        const __nv_bfloat16* s = (prec ? al : ah) + (size_t)nc * 128 + slab * 64 + ch * 8;
        uint32_t d = sbase + (uint32_t)(prec * TILEB + (row * SROW + ch * 8) * 2);
        cpa16(d, s, n < Nn ? 16 : 0);
    }
}

__device__ __forceinline__ void fill_B(uint32_t sbase, const __nv_bfloat16* bh,
                                       const __nv_bfloat16* bl, int slab, int tid) {
#pragma unroll
    for (int it = 0; it < 8; it++) {
        int idx = it * 256 + tid;
        int prec = idx >> 10;
        int rem = idx & 1023;
        int row = rem >> 3;
        int ch = rem & 7;
        const __nv_bfloat16* s = (prec ? bl : bh) + (size_t)row * 128 + slab * 64 + ch * 8;
        uint32_t d = sbase + (uint32_t)(prec * TILEB + (row * SROW + ch * 8) * 2);
        cpa16(d, s, 16);
    }
}

// MMA over one slab. FULL: Ah*Bh + Al*Bh + Ah*Bl.  !FULL: Ah*Bh + Ah*Bl.
template <bool FULL>
__device__ __forceinline__ void mma_slab(uint32_t smem_s, uint32_t abase, float d[2][8][4],
                                         int lane, int wid) {
    int warpM = wid & 3, warpN = wid >> 2;
    int grp = lane >> 3, lr = lane & 7;
    uint32_t aA = smem_s + abase +
        (uint32_t)(((warpM * 32 + lr + (grp & 1) * 8) * SROW + (grp >> 1) * 8) * 2);
    uint32_t aB = smem_s + S_BH +
        (uint32_t)(((warpN * 64 + lr + (grp >> 1) * 8) * SROW + (grp & 1) * 8) * 2);
    const uint32_t MT = 16 * SROW * 2;

#pragma unroll
    for (int ks = 0; ks < 4; ks++) {
        uint32_t kb = (uint32_t)(ks * 32);
        uint32_t ah[2][4], al[2][4], bb[4][4];
#pragma unroll
        for (int mt = 0; mt < 2; mt++) {
            ldsm4(ah[mt][0], ah[mt][1], ah[mt][2], ah[mt][3], aA + mt * MT + kb);
            if (FULL)
                ldsm4(al[mt][0], al[mt][1], al[mt][2], al[mt][3], aA + TILEB + mt * MT + kb);
        }
#pragma unroll
        for (int np = 0; np < 4; np++)
            ldsm4(bb[np][0], bb[np][1], bb[np][2], bb[np][3], aB + np * MT + kb);
        // Ah x Bh
#pragma unroll
        for (int np = 0; np < 4; np++)
#pragma unroll
            for (int mt = 0; mt < 2; mt++) {
                mma16816(d[mt][2 * np][0], d[mt][2 * np][1], d[mt][2 * np][2], d[mt][2 * np][3],
                         ah[mt][0], ah[mt][1], ah[mt][2], ah[mt][3], bb[np][0], bb[np][1]);
                mma16816(d[mt][2 * np + 1][0], d[mt][2 * np + 1][1], d[mt][2 * np + 1][2], d[mt][2 * np + 1][3],
                         ah[mt][0], ah[mt][1], ah[mt][2], ah[mt][3], bb[np][2], bb[np][3]);
            }
        if (FULL) {
            // Al x Bh
#pragma unroll
            for (int np = 0; np < 4; np++)
#pragma unroll
                for (int mt = 0; mt < 2; mt++) {
                    mma16816(d[mt][2 * np][0], d[mt][2 * np][1], d[mt][2 * np][2], d[mt][2 * np][3],
                             al[mt][0], al[mt][1], al[mt][2], al[mt][3], bb[np][0], bb[np][1]);
                    mma16816(d[mt][2 * np + 1][0], d[mt][2 * np + 1][1], d[mt][2 * np + 1][2], d[mt][2 * np + 1][3],
                             al[mt][0], al[mt][1], al[mt][2], al[mt][3], bb[np][2], bb[np][3]);
                }
        }
        // Bl, then Ah x Bl
#pragma unroll
        for (int np = 0; np < 4; np++)
            ldsm4(bb[np][0], bb[np][1], bb[np][2], bb[np][3], aB + TILEB + np * MT + kb);
#pragma unroll
        for (int np = 0; np < 4; np++)
#pragma unroll
            for (int mt = 0; mt < 2; mt++) {
                mma16816(d[mt][2 * np][0], d[mt][2 * np][1], d[mt][2 * np][2], d[mt][2 * np][3],
                         ah[mt][0], ah[mt][1], ah[mt][2], ah[mt][3], bb[np][0], bb[np][1]);
                mma16816(d[mt][2 * np + 1][0], d[mt][2 * np + 1][1], d[mt][2 * np + 1][2], d[mt][2 * np + 1][3],
                         ah[mt][0], ah[mt][1], ah[mt][2], ah[mt][3], bb[np][2], bb[np][3]);
            }
    }
}

// pipelined core: A double-buffered, B refilled between slabs
template <bool FULL>
__device__ __forceinline__ void gemm_core(const __nv_bfloat16* __restrict__ ah,
                                          const __nv_bfloat16* __restrict__ alo,
                                          int n0,
                                          const __nv_bfloat16* __restrict__ bth,
                                          const __nv_bfloat16* __restrict__ btl,
                                          char* smem, float d[2][8][4]) {
    int tid = threadIdx.x, lane = tid & 31, wid = tid >> 5;
    uint32_t smem_s = (uint32_t)__cvta_generic_to_shared(smem);

    fill_B(smem_s + S_BH, bth, btl, 0, tid);
    fill_A<FULL>(smem_s + S_A0H, ah, alo, n0, 0, tid);
    CP_COMMIT();
    fill_A<FULL>(smem_s + S_A1H, ah, alo, n0, 1, tid);
    CP_COMMIT();
    CP_WAIT(1);
    __syncthreads();
    mma_slab<FULL>(smem_s, S_A0H, d, lane, wid);
    __syncthreads();
    fill_B(smem_s + S_BH, bth, btl, 1, tid);
    CP_COMMIT();
    CP_WAIT(0);
    __syncthreads();
    mma_slab<FULL>(smem_s, S_A1H, d, lane, wid);
    __syncthreads();
}

__device__ __forceinline__ void stage_d(float* sd, float d[2][8][4], int lane, int wid) {
    int warpM = wid & 3, warpN = wid >> 2;
    int rq = lane >> 2, cq = (lane & 3) * 2;
#pragma unroll
    for (int mt = 0; mt < 2; mt++) {
        int rl0 = warpM * 32 + mt * 16 + rq;
        int rl1 = rl0 + 8;
#pragma unroll
        for (int nt = 0; nt < 8; nt++) {
            int c = warpN * 64 + nt * 8 + cq;
            *(float2*)&sd[rl0 * SDW + c] = make_float2(d[mt][nt][0], d[mt][nt][1]);
            *(float2*)&sd[rl1 * SDW + c] = make_float2(d[mt][nt][2], d[mt][nt][3]);
        }
    }
}

// ---------------- projection GEMM + fused el/er -----------------------------------
__global__ void __launch_bounds__(256, 2) k_gemm_feat(
    const __nv_bfloat16* __restrict__ xh, const __nv_bfloat16* __restrict__ xl,
    const __nv_bfloat16* __restrict__ bth, const __nv_bfloat16* __restrict__ btl,
    const float* __restrict__ al, const float* __restrict__ ar,
    float* __restrict__ feat, float* __restrict__ el, float* __restrict__ er) {
    extern __shared__ char smem[];
    int tid = threadIdx.x, lane = tid & 31, wid = tid >> 5;
    int p = blockIdx.y;
    int n0 = blockIdx.x * 128;
    float* sal = (float*)(smem + S_AUX0);
    float* sar = (float*)(smem + S_AUX1);
    if (tid < 128) { sal[tid] = al[p * 128 + tid]; sar[tid] = ar[p * 128 + tid]; }

    float d[2][8][4];
#pragma unroll
    for (int mt = 0; mt < 2; mt++)
#pragma unroll
        for (int nt = 0; nt < 8; nt++)
#pragma unroll
            for (int q = 0; q < 4; q++) d[mt][nt][q] = 0.f;

    gemm_core<true>(xh, xl, n0, bth + (size_t)p * 16384, btl + (size_t)p * 16384, smem, d);

    float* sd = (float*)(smem + S_A0H);
    stage_d(sd, d, lane, wid);
    __syncthreads();

    int row = tid >> 1, half = tid & 1;
    int n = n0 + row;
    if (n < Nn) {
        float sel[2] = {0.f, 0.f}, ser[2] = {0.f, 0.f};
        float4* o = (float4*)&feat[((size_t)p * Nn + n) * 128 + half * 64];
#pragma unroll
        for (int q = 0; q < 16; q++) {
            float4 v = *(float4*)&sd[row * SDW + half * 64 + q * 4];
            o[q] = v;
            int hb = q >> 3;
            int c = half * 64 + q * 4;
            sel[hb] = fmaf(v.x, sal[c + 0], sel[hb]);
            sel[hb] = fmaf(v.y, sal[c + 1], sel[hb]);
            sel[hb] = fmaf(v.z, sal[c + 2], sel[hb]);
            sel[hb] = fmaf(v.w, sal[c + 3], sel[hb]);
            ser[hb] = fmaf(v.x, sar[c + 0], ser[hb]);
            ser[hb] = fmaf(v.y, sar[c + 1], ser[hb]);
            ser[hb] = fmaf(v.z, sar[c + 2], ser[hb]);
            ser[hb] = fmaf(v.w, sar[c + 3], ser[hb]);
        }
        *(float2*)&el[((size_t)p * Nn + n) * 4 + half * 2] = make_float2(sel[0], sel[1]);
        *(float2*)&er[((size_t)p * Nn + n) * 4 + half * 2] = make_float2(ser[0], ser[1]);
    }
}

// ---------------- semantic GEMM (2-pass) + tanh/w2 reduce ---------------------------
__global__ void __launch_bounds__(256, 2) k_semgemm(
    const __nv_bfloat16* __restrict__ zh, const __nv_bfloat16* __restrict__ zl,
    const __nv_bfloat16* __restrict__ bth, const __nv_bfloat16* __restrict__ btl,
    const float* __restrict__ b1, const float* __restrict__ w2, float* __restrict__ wsem) {
    extern __shared__ char smem[];
    int tid = threadIdx.x, lane = tid & 31, wid = tid >> 5;
    int p = blockIdx.y;
    int n0 = blockIdx.x * 128;
    float* sb1 = (float*)(smem + S_AUX0);
    float* sw2 = (float*)(smem + S_AUX1);
    float* sred = (float*)(smem + S_RED);
    if (tid < 128) { sb1[tid] = b1[tid]; sw2[tid] = w2[tid]; }

    float d[2][8][4];
#pragma unroll
    for (int mt = 0; mt < 2; mt++)
#pragma unroll
        for (int nt = 0; nt < 8; nt++)
#pragma unroll
            for (int q = 0; q < 4; q++) d[mt][nt][q] = 0.f;

    gemm_core<false>(zh + (size_t)p * Nn * 128, zl, n0, bth, btl, smem, d);

    float* sd = (float*)(smem + S_A0H);
    stage_d(sd, d, lane, wid);
    __syncthreads();

    int row = tid >> 1, half = tid & 1;
    int n = n0 + row;
    float accv = 0.f;
    if (n < Nn) {
#pragma unroll
        for (int q = 0; q < 16; q++) {
            float4 v = *(float4*)&sd[row * SDW + half * 64 + q * 4];
            int c = half * 64 + q * 4;
            accv = fmaf(tanhf(v.x + sb1[c + 0]), sw2[c + 0], accv);
            accv = fmaf(tanhf(v.y + sb1[c + 1]), sw2[c + 1], accv);
            accv = fmaf(tanhf(v.z + sb1[c + 2]), sw2[c + 2], accv);
            accv = fmaf(tanhf(v.w + sb1[c + 3]), sw2[c + 3], accv);
        }
    }
#pragma unroll
    for (int o = 16; o; o >>= 1) accv += __shfl_xor_sync(0xffffffffu, accv, o);
    if (lane == 0) sred[wid] = accv;
    __syncthreads();
    if (tid == 0) {
        float s = 0.f;
#pragma unroll
        for (int i = 0; i < 8; i++) s += sred[i];
        atomicAdd(&wsem[p], s);
    }
}

// ---------------- feature attention: warp per node ----------------------------------
__global__ void k_featatt(const float* __restrict__ h, const float* __restrict__ cf,
                          const float* __restrict__ w1, const float* __restrict__ b1,
                          const float* __restrict__ w2,
                          __nv_bfloat16* __restrict__ xh, __nv_bfloat16* __restrict__ xl) {
    __shared__ float sw1[42 * 16];
    __shared__ float sb1[16], sw2[16];
    __shared__ __align__(16) float sf[8][840];
    __shared__ float ss[8][20];
    int tid = threadIdx.x, wid = tid >> 5, lane = tid & 31;
    for (int i = tid; i < 672; i += 256) sw1[i] = w1[i];
    if (tid < 16) { sb1[tid] = b1[tid]; sw2[tid] = w2[tid]; }
    __syncthreads();
    int n = blockIdx.x * 8 + wid;
    if (n >= Nn) return;

    const float4* fr4 = (const float4*)(cf + (size_t)n * 840);
    float* myf = sf[wid];
    float4* myf4 = (float4*)myf;
    for (int i = lane; i < 210; i += 32) myf4[i] = fr4[i];
    __syncwarp();

    int k = lane & 15;
    for (int j0 = 0; j0 < 20; j0 += 2) {
        int j = j0 + (lane >> 4);
        const float* fj = myf + j * 42;
        float acc = sb1[k];
#pragma unroll
        for (int i = 0; i < 42; i++) acc = fmaf(fj[i], sw1[i * 16 + k], acc);
        float v = tanhf(acc) * sw2[k];
#pragma unroll
        for (int off = 8; off; off >>= 1) v += __shfl_down_sync(0xffffffffu, v, off);
        if (k == 0) ss[wid][j] = v;
    }
    __syncwarp();

    float sc = (lane < 20) ? ss[wid][lane] : -INFINITY;
    float mx = sc;
#pragma unroll
    for (int off = 16; off; off >>= 1) mx = fmaxf(mx, __shfl_xor_sync(0xffffffffu, mx, off));
    float ex = (lane < 20) ? expf(sc - mx) : 0.f;
    float sm = ex;
#pragma unroll
    for (int off = 16; off; off >>= 1) sm += __shfl_xor_sync(0xffffffffu, sm, off);
    float beta = ex / sm;

    float a0 = 0.f, a1 = 0.f;
    for (int j = 0; j < 20; j++) {
        float bj = __shfl_sync(0xffffffffu, beta, j);
        a0 = fmaf(bj, myf[j * 42 + lane], a0);
        if (lane < 10) a1 = fmaf(bj, myf[j * 42 + 32 + lane], a1);
    }
    const float* hr = h + (size_t)n * 86;
    __nv_bfloat16* xhr = xh + (size_t)n * 128;
    __nv_bfloat16* xlr = xl + (size_t)n * 128;
    for (int i = lane; i < 86; i += 32) {
        float v = hr[i];
        __nv_bfloat16 hh = __float2bfloat16(v);
        xhr[i] = hh;
        xlr[i] = __float2bfloat16(v - __bfloat162float(hh));
    }
    {
        __nv_bfloat16 hh = __float2bfloat16(a0);
        xhr[86 + lane] = hh;
        xlr[86 + lane] = __float2bfloat16(a0 - __bfloat162float(hh));
    }
    if (lane < 10) {
        __nv_bfloat16 hh = __float2bfloat16(a1);
        xhr[118 + lane] = hh;
        xlr[118 + lane] = __float2bfloat16(a1 - __bfloat162float(hh));
    }
}

// ---------------- weight prep ---------------------------------------------------------
__global__ void k_wprep(const float* __restrict__ gatW, const float* __restrict__ saw1,
                        __nv_bfloat16* __restrict__ bh, __nv_bfloat16* __restrict__ bl) {
    int idx = blockIdx.x * 256 + threadIdx.x;
    if (idx >= 4 * 16384) return;
    int slot = idx >> 14, rem = idx & 16383;
    int nIdx = rem >> 7, kIdx = rem & 127;
    float v = (slot < 3) ? gatW[slot * 16384 + kIdx * 128 + nIdx] : saw1[kIdx * 128 + nIdx];
    __nv_bfloat16 hh = __float2bfloat16(v);
    bh[idx] = hh;
    bl[idx] = __float2bfloat16(v - __bfloat162float(hh));
}

// ---------------- CSR build (4-way ILP atomics) ----------------------------------------
__global__ void k_count(const int* __restrict__ dst, int* __restrict__ deg) {
    int p = blockIdx.y;
    int base = blockIdx.x * 1024 + threadIdx.x;
#pragma unroll
    for (int j = 0; j < 4; j++) {
        int e = base + j * 256;
        if (e < Ee) atomicAdd(&deg[(size_t)p * Nn + dst[(size_t)p * Ee + e]], 1);
    }
}

__global__ void k_scan(const int* __restrict__ deg, int* __restrict__ off,
                       int* __restrict__ cur) {
    int p = blockIdx.x;
    int tid = threadIdx.x, lane = tid & 31, wid = tid >> 5;
    __shared__ int wsum[32];
    __shared__ int carry;
    if (tid == 0) carry = 0;
    __syncthreads();
    for (int base = 0; base < Nn; base += 1024) {
        int i = base + tid;
        int v = (i < Nn) ? deg[(size_t)p * Nn + i] : 0;
        int xv = v;
#pragma unroll
        for (int o = 1; o < 32; o <<= 1) {
            int t = __shfl_up_sync(0xffffffffu, xv, o);
            if (lane >= o) xv += t;
        }
        if (lane == 31) wsum[wid] = xv;
        __syncthreads();
        if (wid == 0) {
            int y = wsum[lane];
#pragma unroll
            for (int o = 1; o < 32; o <<= 1) {
                int t = __shfl_up_sync(0xffffffffu, y, o);
                if (lane >= o) y += t;
            }
            wsum[lane] = y;
        }
        __syncthreads();
        int wpre = (wid == 0) ? 0 : wsum[wid - 1];
        int excl = carry + wpre + xv - v;
        if (i < Nn) {
            off[(size_t)p * (Nn + 1) + i] = excl;
            cur[(size_t)p * Nn + i] = excl;
        }
        __syncthreads();
        if (tid == 1023) carry = excl + v;
        __syncthreads();
    }
    if (tid == 0) off[(size_t)p * (Nn + 1) + Nn] = carry;
}

__global__ void k_scatter(const int* __restrict__ src, const int* __restrict__ dst,
                          int* __restrict__ cur, int* __restrict__ csrc) {
    int p = blockIdx.y;
    int base = blockIdx.x * 1024 + threadIdx.x;
    int ev[4], dv[4], sv[4];
#pragma unroll
    for (int j = 0; j < 4; j++) {
        ev[j] = base + j * 256;
        if (ev[j] < Ee) {
            dv[j] = dst[(size_t)p * Ee + ev[j]];
            sv[j] = src[(size_t)p * Ee + ev[j]];
        }
    }
#pragma unroll
    for (int j = 0; j < 4; j++) {
        if (ev[j] < Ee) {
            int pos = atomicAdd(&cur[(size_t)p * Nn + dv[j]], 1);
            csrc[(size_t)p * Ee + pos] = sv[j];
        }
    }
}

// ---------------- gather aggregation: warp per (p, dst) -------------------------------
__global__ void k_gather(const int* __restrict__ csrc, const int* __restrict__ off,
                         const float* __restrict__ el, const float* __restrict__ er,
                         const float* __restrict__ feat,
                         __nv_bfloat16* __restrict__ zh, __nv_bfloat16* __restrict__ zl) {
    int p = blockIdx.y;
    int tid = threadIdx.x, wid = tid >> 5, lane = tid & 31;
    int n = blockIdx.x * 8 + wid;
    if (n >= Nn) return;
    long r = (long)p * Nn + n;
    int start = off[(size_t)p * (Nn + 1) + n];
    int end = off[(size_t)p * (Nn + 1) + n + 1];
    float4 acc = make_float4(0.f, 0.f, 0.f, 0.f);
    if (start < end) {
        const int* sp = csrc + (size_t)p * Ee;
        const float4* elp = (const float4*)el + (size_t)p * Nn;
        float4 er4 = ((const float4*)er)[r];

        float4 mx = make_float4(-INFINITY, -INFINITY, -INFINITY, -INFINITY);
        for (int i = start + lane; i < end; i += 32) {
            float4 a = elp[sp[i]];
            float vx = a.x + er4.x; vx = vx > 0.f ? vx : 0.2f * vx;
            float vy = a.y + er4.y; vy = vy > 0.f ? vy : 0.2f * vy;
            float vz = a.z + er4.z; vz = vz > 0.f ? vz : 0.2f * vz;
            float vw = a.w + er4.w; vw = vw > 0.f ? vw : 0.2f * vw;
            mx.x = fmaxf(mx.x, vx); mx.y = fmaxf(mx.y, vy);
            mx.z = fmaxf(mx.z, vz); mx.w = fmaxf(mx.w, vw);
        }
#pragma unroll
        for (int o = 16; o; o >>= 1) {
            mx.x = fmaxf(mx.x, __shfl_xor_sync(0xffffffffu, mx.x, o));
            mx.y = fmaxf(mx.y, __shfl_xor_sync(0xffffffffu, mx.y, o));
            mx.z = fmaxf(mx.z, __shfl_xor_sync(0xffffffffu, mx.z, o));
            mx.w = fmaxf(mx.w, __shfl_xor_sync(0xffffffffu, mx.w, o));
        }

        int head = lane >> 3;
        float4 zs = make_float4(0.f, 0.f, 0.f, 0.f);
        int i = start;
        for (; i + 1 < end; i += 2) {
            int s0 = sp[i], s1 = sp[i + 1];
            float4 a0 = elp[s0], a1 = elp[s1];
            float4 f0 = *(const float4*)&feat[((size_t)p * Nn + s0) * 128 + lane * 4];
            float4 f1 = *(const float4*)&feat[((size_t)p * Nn + s1) * 128 + lane * 4];
            float4 w0, w1;
            float t;
            t = a0.x + er4.x; t = t > 0.f ? t : 0.2f * t; w0.x = __expf(t - mx.x);
            t = a0.y + er4.y; t = t > 0.f ? t : 0.2f * t; w0.y = __expf(t - mx.y);
            t = a0.z + er4.z; t = t > 0.f ? t : 0.2f * t; w0.z = __expf(t - mx.z);
            t = a0.w + er4.w; t = t > 0.f ? t : 0.2f * t; w0.w = __expf(t - mx.w);
            t = a1.x + er4.x; t = t > 0.f ? t : 0.2f * t; w1.x = __expf(t - mx.x);
            t = a1.y + er4.y; t = t > 0.f ? t : 0.2f * t; w1.y = __expf(t - mx.y);
            t = a1.z + er4.z; t = t > 0.f ? t : 0.2f * t; w1.z = __expf(t - mx.z);
            t = a1.w + er4.w; t = t > 0.f ? t : 0.2f * t; w1.w = __expf(t - mx.w);
            zs.x += w0.x + w1.x; zs.y += w0.y + w1.y;
            zs.z += w0.z + w1.z; zs.w += w0.w + w1.w;
            float c0 = head == 0 ? w0.x : head == 1 ? w0.y : head == 2 ? w0.z : w0.w;
            float c1 = head == 0 ? w1.x : head == 1 ? w1.y : head == 2 ? w1.z : w1.w;
            acc.x = fmaf(c0, f0.x, acc.x); acc.x = fmaf(c1, f1.x, acc.x);
            acc.y = fmaf(c0, f0.y, acc.y); acc.y = fmaf(c1, f1.y, acc.y);
            acc.z = fmaf(c0, f0.z, acc.z); acc.z = fmaf(c1, f1.z, acc.z);
            acc.w = fmaf(c0, f0.w, acc.w); acc.w = fmaf(c1, f1.w, acc.w);
        }
        if (i < end) {
            int s0 = sp[i];
            float4 a0 = elp[s0];
            float4 f0 = *(const float4*)&feat[((size_t)p * Nn + s0) * 128 + lane * 4];
            float4 w0;
            float t;
            t = a0.x + er4.x; t = t > 0.f ? t : 0.2f * t; w0.x = __expf(t - mx.x);
            t = a0.y + er4.y; t = t > 0.f ? t : 0.2f * t; w0.y = __expf(t - mx.y);
            t = a0.z + er4.z; t = t > 0.f ? t : 0.2f * t; w0.z = __expf(t - mx.z);
            t = a0.w + er4.w; t = t > 0.f ? t : 0.2f * t; w0.w = __expf(t - mx.w);
            zs.x += w0.x; zs.y += w0.y; zs.z += w0.z; zs.w += w0.w;
            float c0 = head == 0 ? w0.x : head == 1 ? w0.y : head == 2 ? w0.z : w0.w;
            acc.x = fmaf(c0, f0.x, acc.x);
            acc.y = fmaf(c0, f0.y, acc.y);
            acc.z = fmaf(c0, f0.z, acc.z);
            acc.w = fmaf(c0, f0.w, acc.w);
        }
        float zsel = head == 0 ? zs.x : head == 1 ? zs.y : head == 2 ? zs.z : zs.w;
        float inv = 1.f / zsel;
        acc.x *= inv; acc.y *= inv; acc.z *= inv; acc.w *= inv;
        acc.x = acc.x > 0.f ? acc.x : expm1f(acc.x);
        acc.y = acc.y > 0.f ? acc.y : expm1f(acc.y);
        acc.z = acc.z > 0.f ? acc.z : expm1f(acc.z);
        acc.w = acc.w > 0.f ? acc.w : expm1f(acc.w);
    }
    __nv_bfloat16 hv[4], lv[4];
#pragma unroll
    for (int q = 0; q < 4; q++) {
        float v = (&acc.x)[q];
        __nv_bfloat16 hh = __float2bfloat16(v);
        hv[q] = hh;
        lv[q] = __float2bfloat16(v - __bfloat162float(hh));
    }
    *(uint2*)&zh[(size_t)r * 128 + lane * 4] = *(uint2*)hv;
    *(uint2*)&zl[(size_t)r * 128 + lane * 4] = *(uint2*)lv;
}

// ---------------- softmax over meta-paths + combine -----------------------------------
__global__ void k_bsem(const float* __restrict__ wsem, float* __restrict__ bsem) {
    float w0 = wsem[0] / (float)Nn, w1 = wsem[1] / (float)Nn, w2 = wsem[2] / (float)Nn;
    float m = fmaxf(w0, fmaxf(w1, w2));
    float e0 = expf(w0 - m), e1 = expf(w1 - m), e2 = expf(w2 - m);
    float s = e0 + e1 + e2;
    bsem[0] = e0 / s; bsem[1] = e1 / s; bsem[2] = e2 / s;
}

__global__ void k_comb(const __nv_bfloat16* __restrict__ zh, const __nv_bfloat16* __restrict__ zl,
                       const float* __restrict__ bsem, float* __restrict__ out) {
    long i = (long)blockIdx.x * 256 + threadIdx.x;
    if (i >= (long)Nn * 32) return;
    float b[3] = {bsem[0], bsem[1], bsem[2]};
    float4 o = make_float4(0.f, 0.f, 0.f, 0.f);
#pragma unroll
    for (int p = 0; p < 3; p++) {
        size_t base = (size_t)p * Nn * 128 + i * 4;
        uint2 uh = *(const uint2*)&zh[base];
        uint2 ul = *(const uint2*)&zl[base];
        float2 h0 = __bfloat1622float2(*(__nv_bfloat162*)&uh.x);
        float2 h1 = __bfloat1622float2(*(__nv_bfloat162*)&uh.y);
        float2 l0 = __bfloat1622float2(*(__nv_bfloat162*)&ul.x);
        float2 l1 = __bfloat1622float2(*(__nv_bfloat162*)&ul.y);
        o.x = fmaf(b[p], h0.x + l0.x, o.x);
        o.y = fmaf(b[p], h0.y + l0.y, o.y);
        o.z = fmaf(b[p], h1.x + l1.x, o.z);
        o.w = fmaf(b[p], h1.y + l1.y, o.w);
    }
    ((float4*)out)[i] = o;
}

// ---------------- launch ----------------------------------------------------------------
extern "C" void kernel_launch(void* const* d_in, const int* in_sizes, int n_in,
                              void* d_out, int out_size) {
    const float* h      = (const float*)d_in[0];
    const float* cf     = (const float*)d_in[1];
    const float* fa_w1  = (const float*)d_in[2];
    const float* fa_b1  = (const float*)d_in[3];
    const float* fa_w2  = (const float*)d_in[4];
    const float* gat_W  = (const float*)d_in[5];
    const float* attn_l = (const float*)d_in[6];
    const float* attn_r = (const float*)d_in[7];
    const float* sa_w1  = (const float*)d_in[8];
    const float* sa_b1  = (const float*)d_in[9];
    const float* sa_w2  = (const float*)d_in[10];
    const int*   src    = (const int*)d_in[11];
    const int*   dst    = (const int*)d_in[12];
    float* out = (float*)d_out;

    float *pfeat, *pel, *per, *pwsem, *pbsem;
    int *pdeg, *poff, *pcur, *pcsrc;
    __nv_bfloat16 *pbh, *pbl, *pxh, *pxl, *pzh, *pzl;
    cudaGetSymbolAddress((void**)&pxh, g_x_hi);
    cudaGetSymbolAddress((void**)&pxl, g_x_lo);
    cudaGetSymbolAddress((void**)&pfeat, g_feat);
    cudaGetSymbolAddress((void**)&pzh, g_z_hi);
    cudaGetSymbolAddress((void**)&pzl, g_z_lo);
    cudaGetSymbolAddress((void**)&pel, g_el);
    cudaGetSymbolAddress((void**)&per, g_er);
    cudaGetSymbolAddress((void**)&pdeg, g_deg);
    cudaGetSymbolAddress((void**)&poff, g_off);
    cudaGetSymbolAddress((void**)&pcur, g_cur);
    cudaGetSymbolAddress((void**)&pcsrc, g_csrc);
    cudaGetSymbolAddress((void**)&pbh, g_bt_hi);
    cudaGetSymbolAddress((void**)&pbl, g_bt_lo);
    cudaGetSymbolAddress((void**)&pwsem, g_wsem);
    cudaGetSymbolAddress((void**)&pbsem, g_bsem);

    cudaFuncSetAttribute(k_gemm_feat, cudaFuncAttributeMaxDynamicSharedMemorySize, SMEM_TOT);
    cudaFuncSetAttribute(k_semgemm, cudaFuncAttributeMaxDynamicSharedMemorySize, SMEM_TOT);

    cudaMemsetAsync(pdeg, 0, sizeof(int) * (size_t)Pp * Nn, 0);
    cudaMemsetAsync(pwsem, 0, sizeof(float) * Pp, 0);

    k_wprep<<<(4 * 16384 + 255) / 256, 256>>>(gat_W, sa_w1, pbh, pbl);
    k_featatt<<<(Nn + 7) / 8, 256>>>(h, cf, fa_w1, fa_b1, fa_w2, pxh, pxl);

    dim3 ge4((Ee + 1023) / 1024, Pp);
    k_count<<<ge4, 256>>>(dst, pdeg);

    dim3 gg((Nn + 127) / 128, Pp);
    k_gemm_feat<<<gg, 256, SMEM_TOT>>>(pxh, pxl, pbh, pbl, attn_l, attn_r, pfeat, pel, per);

    k_scan<<<Pp, 1024>>>(pdeg, poff, pcur);
    k_scatter<<<ge4, 256>>>(src, dst, pcur, pcsrc);

    dim3 gn((Nn + 7) / 8, Pp);
    k_gather<<<gn, 256>>>(pcsrc, poff, pel, per, pfeat, pzh, pzl);

    k_semgemm<<<gg, 256, SMEM_TOT>>>(pzh, pzl, pbh + 3 * 16384, pbl + 3 * 16384, sa_b1, sa_w2, pwsem);
    k_bsem<<<1, 1>>>(pwsem, pbsem);
    k_comb<<<(unsigned)(((long)Nn * 32 + 255) / 256), 256>>>(pzh, pzl, pbsem, out);
}